// round 3
// baseline (speedup 1.0000x reference)
#include <cuda_runtime.h>
#include <cstddef>

#define S_TOK 8192
#define DIM 1280
#define DIM3 3840
#define NH 16
#define DH 80
#define NSEG 8
#define SEGLEN 1024

// Scratch (device globals: allocation-free per harness rules)
__device__ float g_qkv[S_TOK * DIM3];   // raw qkv = hs @ qkv_w^T + b
__device__ float g_q[S_TOK * DIM];      // roped Q, [s][h*dh+d]
__device__ float g_k[S_TOK * DIM];      // roped K
__device__ float g_attn[S_TOK * DIM];   // attention output

// ---------------------------------------------------------------------------
// SGEMM (NT): C[M,N] = A[M,K] @ B[N,K]^T + bias[N]
// BM=BN=128, BK=8, 256 threads, 8x8 microtile per thread.
// M,N multiples of 128; K multiple of 8 (holds for all uses here).
// ---------------------------------------------------------------------------
__global__ __launch_bounds__(256) void sgemm_nt_bias(
    const float* __restrict__ A, const float* __restrict__ B,
    const float* __restrict__ bias, float* __restrict__ C,
    int M, int N, int K)
{
    __shared__ float As[8][128];
    __shared__ float Bs[8][128];

    const int bm = blockIdx.y * 128;
    const int bn = blockIdx.x * 128;
    const int tid = threadIdx.x;
    const int tx = tid & 15;
    const int ty = tid >> 4;
    const int lr = tid >> 1;           // 0..127
    const int lc = (tid & 1) << 2;     // 0 or 4

    const float* Ag = A + (size_t)(bm + lr) * K + lc;
    const float* Bg = B + (size_t)(bn + lr) * K + lc;

    float acc[8][8];
#pragma unroll
    for (int i = 0; i < 8; i++)
#pragma unroll
        for (int j = 0; j < 8; j++) acc[i][j] = 0.f;

    for (int k0 = 0; k0 < K; k0 += 8) {
        float4 a4 = *(const float4*)(Ag + k0);
        float4 b4 = *(const float4*)(Bg + k0);
        As[lc + 0][lr] = a4.x; As[lc + 1][lr] = a4.y;
        As[lc + 2][lr] = a4.z; As[lc + 3][lr] = a4.w;
        Bs[lc + 0][lr] = b4.x; Bs[lc + 1][lr] = b4.y;
        Bs[lc + 2][lr] = b4.z; Bs[lc + 3][lr] = b4.w;
        __syncthreads();
#pragma unroll
        for (int k = 0; k < 8; k++) {
            float ar[8], br[8];
            *(float4*)&ar[0] = *(const float4*)&As[k][ty * 8];
            *(float4*)&ar[4] = *(const float4*)&As[k][ty * 8 + 4];
            *(float4*)&br[0] = *(const float4*)&Bs[k][tx * 8];
            *(float4*)&br[4] = *(const float4*)&Bs[k][tx * 8 + 4];
#pragma unroll
            for (int i = 0; i < 8; i++)
#pragma unroll
                for (int j = 0; j < 8; j++)
                    acc[i][j] = fmaf(ar[i], br[j], acc[i][j]);
        }
        __syncthreads();
    }

#pragma unroll
    for (int i = 0; i < 8; i++) {
        const int row = bm + ty * 8 + i;
        float* Crow = C + (size_t)row * N + bn + tx * 8;
#pragma unroll
        for (int j = 0; j < 8; j += 4) {
            float4 o;
            o.x = acc[i][j + 0] + bias[bn + tx * 8 + j + 0];
            o.y = acc[i][j + 1] + bias[bn + tx * 8 + j + 1];
            o.z = acc[i][j + 2] + bias[bn + tx * 8 + j + 2];
            o.w = acc[i][j + 3] + bias[bn + tx * 8 + j + 3];
            *(float4*)(Crow + j) = o;
        }
    }
}

// ---------------------------------------------------------------------------
// RoPE: q/k <- q*cos + rotate_half(q)*sin. rotate_half pairs d with d +/- 40.
// ---------------------------------------------------------------------------
__global__ void rope_kernel(const float* __restrict__ cosp,
                            const float* __restrict__ sinp)
{
    int idx = blockIdx.x * blockDim.x + threadIdx.x;
    if (idx >= S_TOK * DIM) return;
    int s = idx / DIM;
    int c = idx - s * DIM;
    int d = c % DH;
    float cv = cosp[s * DH + d];
    float sv = sinp[s * DH + d];
    const float* row = g_qkv + (size_t)s * DIM3;
    float qv = row[c];
    float kv = row[DIM + c];
    float qr, kr;
    if (d < DH / 2) {
        qr = -row[c + DH / 2];
        kr = -row[DIM + c + DH / 2];
    } else {
        qr = row[c - DH / 2];
        kr = row[DIM + c - DH / 2];
    }
    g_q[idx] = fmaf(qv, cv, qr * sv);
    g_k[idx] = fmaf(kv, cv, kr * sv);
}

// ---------------------------------------------------------------------------
// Flash attention (fp32). One block per (seg, head, 64-row Q tile).
// 256 threads as 16x16 grid; each thread: 4 S-rows x 4 S-cols, O: 4 rows x 5 cols.
// smem: Qs[80][68], Ks[80][68] (k-major, padded to mult-of-4 for float4),
//       Vs[64][80], Ps[64][68].
// ---------------------------------------------------------------------------
#define QK_LD 68
#define P_LD 68
#define ATT_SMEM ((80 * QK_LD * 2 + 64 * 80 + 64 * P_LD) * 4)

__global__ __launch_bounds__(256) void attn_kernel()
{
    extern __shared__ float sm[];
    float* Qs = sm;                       // [80][QK_LD]
    float* Ks = Qs + 80 * QK_LD;          // [80][QK_LD]
    float* Vs = Ks + 80 * QK_LD;          // [64][80]
    float* Ps = Vs + 64 * 80;             // [64][P_LD]

    const int qb = blockIdx.x;
    const int h = blockIdx.y;
    const int seg = blockIdx.z;
    const int tid = threadIdx.x;
    const int tx = tid & 15;
    const int ty = tid >> 4;
    const int s0 = seg * SEGLEN + qb * 64;
    const int hoff = h * DH;

    // Load Q tile, k-major
    for (int i = tid; i < 64 * 80; i += 256) {
        int m = i / 80, k = i - m * 80;
        Qs[k * QK_LD + m] = g_q[(size_t)(s0 + m) * DIM + hoff + k];
    }

    float mrow[4], lrow[4], acc[4][5];
#pragma unroll
    for (int i = 0; i < 4; i++) {
        mrow[i] = -1e30f;
        lrow[i] = 0.f;
#pragma unroll
        for (int j = 0; j < 5; j++) acc[i][j] = 0.f;
    }
    const float scale = 0.11180339887498949f; // 1/sqrt(80)

    for (int n0 = 0; n0 < SEGLEN; n0 += 64) {
        __syncthreads(); // previous iteration's smem reads complete
        const int skb = seg * SEGLEN + n0;
        for (int i = tid; i < 64 * 80; i += 256) {
            int n = i / 80, k = i - n * 80;
            Ks[k * QK_LD + n] = g_k[(size_t)(skb + n) * DIM + hoff + k];
            Vs[n * 80 + k] = g_qkv[(size_t)(skb + n) * DIM3 + 2 * DIM + hoff + k];
        }
        __syncthreads();

        // S = Q K^T  (4x4 per thread)
        float sv[4][4];
#pragma unroll
        for (int i = 0; i < 4; i++)
#pragma unroll
            for (int j = 0; j < 4; j++) sv[i][j] = 0.f;

#pragma unroll 4
        for (int k = 0; k < 80; k++) {
            float4 a = *(const float4*)&Qs[k * QK_LD + 4 * ty];
            float4 b = *(const float4*)&Ks[k * QK_LD + 4 * tx];
            float av[4] = {a.x, a.y, a.z, a.w};
            float bv[4] = {b.x, b.y, b.z, b.w};
#pragma unroll
            for (int i = 0; i < 4; i++)
#pragma unroll
                for (int j = 0; j < 4; j++)
                    sv[i][j] = fmaf(av[i], bv[j], sv[i][j]);
        }

        // Online softmax per row (reduce across tx group of 16 lanes)
#pragma unroll
        for (int i = 0; i < 4; i++) {
#pragma unroll
            for (int j = 0; j < 4; j++) sv[i][j] *= scale;
            float rmax = fmaxf(fmaxf(sv[i][0], sv[i][1]), fmaxf(sv[i][2], sv[i][3]));
#pragma unroll
            for (int m = 8; m; m >>= 1)
                rmax = fmaxf(rmax, __shfl_xor_sync(0xffffffffu, rmax, m));
            float mnew = fmaxf(mrow[i], rmax);
            float corr = __expf(mrow[i] - mnew);
            mrow[i] = mnew;
            float rsum = 0.f;
#pragma unroll
            for (int j = 0; j < 4; j++) {
                float p = __expf(sv[i][j] - mnew);
                sv[i][j] = p;
                rsum += p;
            }
#pragma unroll
            for (int m = 8; m; m >>= 1)
                rsum += __shfl_xor_sync(0xffffffffu, rsum, m);
            lrow[i] = lrow[i] * corr + rsum;
#pragma unroll
            for (int j = 0; j < 5; j++) acc[i][j] *= corr;
        }

        // Write P (n-major) for PV gemm
#pragma unroll
        for (int i = 0; i < 4; i++)
#pragma unroll
            for (int j = 0; j < 4; j++)
                Ps[(4 * tx + j) * P_LD + 4 * ty + i] = sv[i][j];
        __syncthreads();

        // O += P @ V  (4 rows x 5 cols per thread; cols 16*j + tx)
#pragma unroll 2
        for (int n = 0; n < 64; n++) {
            float4 p4 = *(const float4*)&Ps[n * P_LD + 4 * ty];
            float pv[4] = {p4.x, p4.y, p4.z, p4.w};
#pragma unroll
            for (int j = 0; j < 5; j++) {
                float v = Vs[n * 80 + 16 * j + tx];
#pragma unroll
                for (int i = 0; i < 4; i++)
                    acc[i][j] = fmaf(pv[i], v, acc[i][j]);
            }
        }
    }

#pragma unroll
    for (int i = 0; i < 4; i++) {
        float inv = 1.f / lrow[i];
#pragma unroll
        for (int j = 0; j < 5; j++)
            g_attn[(size_t)(s0 + 4 * ty + i) * DIM + hoff + 16 * j + tx] =
                acc[i][j] * inv;
    }
}

// ---------------------------------------------------------------------------
extern "C" void kernel_launch(void* const* d_in, const int* in_sizes, int n_in,
                              void* d_out, int out_size)
{
    const float* hs     = (const float*)d_in[0];
    const float* cosp   = (const float*)d_in[1];
    const float* sinp   = (const float*)d_in[2];
    const float* qkv_w  = (const float*)d_in[3];
    const float* qkv_b  = (const float*)d_in[4];
    const float* proj_w = (const float*)d_in[5];
    const float* proj_b = (const float*)d_in[6];
    float* out = (float*)d_out;

    float *qkv_ptr, *attn_ptr;
    cudaGetSymbolAddress((void**)&qkv_ptr, g_qkv);
    cudaGetSymbolAddress((void**)&attn_ptr, g_attn);

    // 1) QKV GEMM + bias
    dim3 g1(DIM3 / 128, S_TOK / 128);
    sgemm_nt_bias<<<g1, 256>>>(hs, qkv_w, qkv_b, qkv_ptr, S_TOK, DIM3, DIM);

    // 2) RoPE on Q,K
    int total = S_TOK * DIM;
    rope_kernel<<<(total + 255) / 256, 256>>>(cosp, sinp);

    // 3) Flash attention per (seg, head, q-tile)
    cudaFuncSetAttribute(attn_kernel,
                         cudaFuncAttributeMaxDynamicSharedMemorySize, ATT_SMEM);
    dim3 g2(SEGLEN / 64, NH, NSEG);
    attn_kernel<<<g2, 256, ATT_SMEM>>>();

    // 4) Output projection + bias
    dim3 g3(DIM / 128, S_TOK / 128);
    sgemm_nt_bias<<<g3, 256>>>(attn_ptr, proj_w, proj_b, out, S_TOK, DIM, DIM);
}

// round 5
// speedup vs baseline: 1.0640x; 1.0640x over previous
#include <cuda_runtime.h>
#include <cstdint>
#include <cstddef>

#define S_TOK 8192
#define DIM 1280
#define DIM3 3840
#define NH 16
#define DH 80
#define NSEG 8
#define SEGLEN 1024

// Scratch (device globals: allocation-free per harness rules)
__device__ float g_qkv[S_TOK * DIM3];   // raw qkv = hs @ qkv_w^T + b
__device__ float g_q[S_TOK * DIM];      // roped Q
__device__ float g_k[S_TOK * DIM];      // roped K
__device__ float g_attn[S_TOK * DIM];   // attention output

// ---------------------------------------------------------------------------
// tf32 helpers (baseline PTX, no arch-specific features)
// ---------------------------------------------------------------------------
__device__ __forceinline__ uint32_t f2tf32(float x) {
    uint32_t r;
    asm("cvt.rna.tf32.f32 %0, %1;" : "=r"(r) : "f"(x));
    return r;
}

__device__ __forceinline__ void mma_tf32(float* c, const uint32_t* a, const uint32_t* b) {
    asm volatile(
        "mma.sync.aligned.m16n8k8.row.col.f32.tf32.tf32.f32 "
        "{%0,%1,%2,%3}, {%4,%5,%6,%7}, {%8,%9}, {%0,%1,%2,%3};"
        : "+f"(c[0]), "+f"(c[1]), "+f"(c[2]), "+f"(c[3])
        : "r"(a[0]), "r"(a[1]), "r"(a[2]), "r"(a[3]), "r"(b[0]), "r"(b[1]));
}

// ---------------------------------------------------------------------------
// tf32 tensor-core GEMM (NT): C[M,N] = A[M,K] @ B[N,K]^T + bias[N]
// BM=BN=128, BK=16, 256 threads = 8 warps (2 M x 4 N), warp tile 64x32.
// Double-buffered smem, LD=20 pad (conflict-free fragment gather).
// M,N multiples of 128; K multiple of 16.
// ---------------------------------------------------------------------------
#define GLD 20

__global__ __launch_bounds__(256) void gemm_tf32_mma(
    const float* __restrict__ A, const float* __restrict__ B,
    const float* __restrict__ bias, float* __restrict__ C,
    int N, int K)
{
    __shared__ uint32_t As[2][128][GLD];
    __shared__ uint32_t Bs[2][128][GLD];

    const int tid = threadIdx.x;
    const int lane = tid & 31;
    const int wid = tid >> 5;
    const int wm = (wid & 1) * 64;    // warp M origin in tile
    const int wn = (wid >> 1) * 32;   // warp N origin in tile
    const int bm = blockIdx.y * 128;
    const int bn = blockIdx.x * 128;

    // global load mapping: each thread 8 floats of A and of B per tile
    const int lrow = tid >> 1;            // 0..127
    const int lhalf = (tid & 1) * 8;      // 0 or 8
    const float* Ag = A + (size_t)(bm + lrow) * K + lhalf;
    const float* Bg = B + (size_t)(bn + lrow) * K + lhalf;

    float acc[4][4][4];
#pragma unroll
    for (int i = 0; i < 4; i++)
#pragma unroll
        for (int j = 0; j < 4; j++)
#pragma unroll
            for (int c = 0; c < 4; c++) acc[i][j][c] = 0.f;

#define STS_TILE(buf, va0, va1, vb0, vb1) do {                               \
    uint4 _ua, _ub;                                                          \
    _ua.x = f2tf32((va0).x); _ua.y = f2tf32((va0).y);                        \
    _ua.z = f2tf32((va0).z); _ua.w = f2tf32((va0).w);                        \
    *(uint4*)&As[buf][lrow][lhalf] = _ua;                                    \
    _ua.x = f2tf32((va1).x); _ua.y = f2tf32((va1).y);                        \
    _ua.z = f2tf32((va1).z); _ua.w = f2tf32((va1).w);                        \
    *(uint4*)&As[buf][lrow][lhalf + 4] = _ua;                                \
    _ub.x = f2tf32((vb0).x); _ub.y = f2tf32((vb0).y);                        \
    _ub.z = f2tf32((vb0).z); _ub.w = f2tf32((vb0).w);                        \
    *(uint4*)&Bs[buf][lrow][lhalf] = _ub;                                    \
    _ub.x = f2tf32((vb1).x); _ub.y = f2tf32((vb1).y);                        \
    _ub.z = f2tf32((vb1).z); _ub.w = f2tf32((vb1).w);                        \
    *(uint4*)&Bs[buf][lrow][lhalf + 4] = _ub;                                \
} while (0)

    // preload tile 0
    {
        float4 a0 = *(const float4*)(Ag);
        float4 a1 = *(const float4*)(Ag + 4);
        float4 b0 = *(const float4*)(Bg);
        float4 b1 = *(const float4*)(Bg + 4);
        STS_TILE(0, a0, a1, b0, b1);
    }
    __syncthreads();

    const int NT = K / 16;
    const int r = lane >> 2;
    const int cq = lane & 3;

    for (int kt = 0; kt < NT; ++kt) {
        const int buf = kt & 1;
        float4 na0, na1, nb0, nb1;
        const bool more = (kt + 1 < NT);
        if (more) {
            const float* Ap = Ag + (kt + 1) * 16;
            const float* Bp = Bg + (kt + 1) * 16;
            na0 = *(const float4*)(Ap);
            na1 = *(const float4*)(Ap + 4);
            nb0 = *(const float4*)(Bp);
            nb1 = *(const float4*)(Bp + 4);
        }

#pragma unroll
        for (int ks = 0; ks < 2; ++ks) {
            const int kc = ks * 8 + cq;
            uint32_t af[4][4], bf[4][2];
#pragma unroll
            for (int i = 0; i < 4; i++) {
                af[i][0] = As[buf][wm + i * 16 + r][kc];
                af[i][1] = As[buf][wm + i * 16 + r + 8][kc];
                af[i][2] = As[buf][wm + i * 16 + r][kc + 4];
                af[i][3] = As[buf][wm + i * 16 + r + 8][kc + 4];
            }
#pragma unroll
            for (int j = 0; j < 4; j++) {
                bf[j][0] = Bs[buf][wn + j * 8 + r][kc];
                bf[j][1] = Bs[buf][wn + j * 8 + r][kc + 4];
            }
#pragma unroll
            for (int i = 0; i < 4; i++)
#pragma unroll
                for (int j = 0; j < 4; j++)
                    mma_tf32(acc[i][j], af[i], bf[j]);
        }

        if (more) {
            STS_TILE(buf ^ 1, na0, na1, nb0, nb1);
        }
        __syncthreads();
    }
#undef STS_TILE

    // Epilogue: per (i,j) C rows bm+wm+i*16+{r, r+8}, cols bn+wn+j*8+cq*2 (+1)
#pragma unroll
    for (int i = 0; i < 4; i++) {
        const int row0 = bm + wm + i * 16 + r;
#pragma unroll
        for (int j = 0; j < 4; j++) {
            const int col = bn + wn + j * 8 + cq * 2;
            const float b0 = bias[col], b1 = bias[col + 1];
            float2 v;
            v.x = acc[i][j][0] + b0;
            v.y = acc[i][j][1] + b1;
            *(float2*)(C + (size_t)row0 * N + col) = v;
            v.x = acc[i][j][2] + b0;
            v.y = acc[i][j][3] + b1;
            *(float2*)(C + (size_t)(row0 + 8) * N + col) = v;
        }
    }
}

// ---------------------------------------------------------------------------
// RoPE: q/k <- q*cos + rotate_half(q)*sin.
// ---------------------------------------------------------------------------
__global__ void rope_kernel(const float* __restrict__ cosp,
                            const float* __restrict__ sinp)
{
    int idx = blockIdx.x * blockDim.x + threadIdx.x;
    if (idx >= S_TOK * DIM) return;
    int s = idx / DIM;
    int c = idx - s * DIM;
    int d = c % DH;
    float cv = cosp[s * DH + d];
    float sv = sinp[s * DH + d];
    const float* row = g_qkv + (size_t)s * DIM3;
    float qv = row[c];
    float kv = row[DIM + c];
    float qr, kr;
    if (d < DH / 2) {
        qr = -row[c + DH / 2];
        kr = -row[DIM + c + DH / 2];
    } else {
        qr = row[c - DH / 2];
        kr = row[DIM + c - DH / 2];
    }
    g_q[idx] = fmaf(qv, cv, qr * sv);
    g_k[idx] = fmaf(kv, cv, kr * sv);
}

// ---------------------------------------------------------------------------
// Flash attention (fp32 SIMT), as in passing round 3.
// ---------------------------------------------------------------------------
#define QK_LD 68
#define P_LD 68
#define ATT_SMEM ((80 * QK_LD * 2 + 64 * 80 + 64 * P_LD) * 4)

__global__ __launch_bounds__(256) void attn_kernel()
{
    extern __shared__ float sm[];
    float* Qs = sm;
    float* Ks = Qs + 80 * QK_LD;
    float* Vs = Ks + 80 * QK_LD;
    float* Ps = Vs + 64 * 80;

    const int qb = blockIdx.x;
    const int h = blockIdx.y;
    const int seg = blockIdx.z;
    const int tid = threadIdx.x;
    const int tx = tid & 15;
    const int ty = tid >> 4;
    const int s0 = seg * SEGLEN + qb * 64;
    const int hoff = h * DH;

    for (int i = tid; i < 64 * 80; i += 256) {
        int m = i / 80, k = i - m * 80;
        Qs[k * QK_LD + m] = g_q[(size_t)(s0 + m) * DIM + hoff + k];
    }

    float mrow[4], lrow[4], acc[4][5];
#pragma unroll
    for (int i = 0; i < 4; i++) {
        mrow[i] = -1e30f;
        lrow[i] = 0.f;
#pragma unroll
        for (int j = 0; j < 5; j++) acc[i][j] = 0.f;
    }
    const float scale = 0.11180339887498949f;

    for (int n0 = 0; n0 < SEGLEN; n0 += 64) {
        __syncthreads();
        const int skb = seg * SEGLEN + n0;
        for (int i = tid; i < 64 * 80; i += 256) {
            int n = i / 80, k = i - n * 80;
            Ks[k * QK_LD + n] = g_k[(size_t)(skb + n) * DIM + hoff + k];
            Vs[n * 80 + k] = g_qkv[(size_t)(skb + n) * DIM3 + 2 * DIM + hoff + k];
        }
        __syncthreads();

        float sv[4][4];
#pragma unroll
        for (int i = 0; i < 4; i++)
#pragma unroll
            for (int j = 0; j < 4; j++) sv[i][j] = 0.f;

#pragma unroll 4
        for (int k = 0; k < 80; k++) {
            float4 a = *(const float4*)&Qs[k * QK_LD + 4 * ty];
            float4 b = *(const float4*)&Ks[k * QK_LD + 4 * tx];
            float av[4] = {a.x, a.y, a.z, a.w};
            float bv[4] = {b.x, b.y, b.z, b.w};
#pragma unroll
            for (int i = 0; i < 4; i++)
#pragma unroll
                for (int j = 0; j < 4; j++)
                    sv[i][j] = fmaf(av[i], bv[j], sv[i][j]);
        }

#pragma unroll
        for (int i = 0; i < 4; i++) {
#pragma unroll
            for (int j = 0; j < 4; j++) sv[i][j] *= scale;
            float rmax = fmaxf(fmaxf(sv[i][0], sv[i][1]), fmaxf(sv[i][2], sv[i][3]));
#pragma unroll
            for (int m = 8; m; m >>= 1)
                rmax = fmaxf(rmax, __shfl_xor_sync(0xffffffffu, rmax, m));
            float mnew = fmaxf(mrow[i], rmax);
            float corr = __expf(mrow[i] - mnew);
            mrow[i] = mnew;
            float rsum = 0.f;
#pragma unroll
            for (int j = 0; j < 4; j++) {
                float p = __expf(sv[i][j] - mnew);
                sv[i][j] = p;
                rsum += p;
            }
#pragma unroll
            for (int m = 8; m; m >>= 1)
                rsum += __shfl_xor_sync(0xffffffffu, rsum, m);
            lrow[i] = lrow[i] * corr + rsum;
#pragma unroll
            for (int j = 0; j < 5; j++) acc[i][j] *= corr;
        }

#pragma unroll
        for (int i = 0; i < 4; i++)
#pragma unroll
            for (int j = 0; j < 4; j++)
                Ps[(4 * tx + j) * P_LD + 4 * ty + i] = sv[i][j];
        __syncthreads();

#pragma unroll 2
        for (int n = 0; n < 64; n++) {
            float4 p4 = *(const float4*)&Ps[n * P_LD + 4 * ty];
            float pv[4] = {p4.x, p4.y, p4.z, p4.w};
#pragma unroll
            for (int j = 0; j < 5; j++) {
                float v = Vs[n * 80 + 16 * j + tx];
#pragma unroll
                for (int i = 0; i < 4; i++)
                    acc[i][j] = fmaf(pv[i], v, acc[i][j]);
            }
        }
    }

#pragma unroll
    for (int i = 0; i < 4; i++) {
        float inv = 1.f / lrow[i];
#pragma unroll
        for (int j = 0; j < 5; j++)
            g_attn[(size_t)(s0 + 4 * ty + i) * DIM + hoff + 16 * j + tx] =
                acc[i][j] * inv;
    }
}

// ---------------------------------------------------------------------------
extern "C" void kernel_launch(void* const* d_in, const int* in_sizes, int n_in,
                              void* d_out, int out_size)
{
    const float* hs     = (const float*)d_in[0];
    const float* cosp   = (const float*)d_in[1];
    const float* sinp   = (const float*)d_in[2];
    const float* qkv_w  = (const float*)d_in[3];
    const float* qkv_b  = (const float*)d_in[4];
    const float* proj_w = (const float*)d_in[5];
    const float* proj_b = (const float*)d_in[6];
    float* out = (float*)d_out;

    float *qkv_ptr, *attn_ptr;
    cudaGetSymbolAddress((void**)&qkv_ptr, g_qkv);
    cudaGetSymbolAddress((void**)&attn_ptr, g_attn);

    // 1) QKV GEMM + bias (tf32 tensor cores)
    dim3 g1(DIM3 / 128, S_TOK / 128);
    gemm_tf32_mma<<<g1, 256>>>(hs, qkv_w, qkv_b, qkv_ptr, DIM3, DIM);

    // 2) RoPE on Q,K
    int total = S_TOK * DIM;
    rope_kernel<<<(total + 255) / 256, 256>>>(cosp, sinp);

    // 3) Flash attention
    cudaFuncSetAttribute(attn_kernel,
                         cudaFuncAttributeMaxDynamicSharedMemorySize, ATT_SMEM);
    dim3 g2(SEGLEN / 64, NH, NSEG);
    attn_kernel<<<g2, 256, ATT_SMEM>>>();

    // 4) Output projection + bias (tf32 tensor cores)
    dim3 g3(DIM / 128, S_TOK / 128);
    gemm_tf32_mma<<<g3, 256>>>(attn_ptr, proj_w, proj_b, out, DIM, DIM);
}

// round 6
// speedup vs baseline: 2.7493x; 2.5840x over previous
#include <cuda_runtime.h>
#include <cstdint>
#include <cstddef>

#define S_TOK 8192
#define DIM 1280
#define DIM3 3840
#define NH 16
#define DH 80
#define NSEG 8
#define SEGLEN 1024

// Scratch (device globals: allocation-free per harness rules)
__device__ float g_qkv[S_TOK * DIM3];   // raw qkv = hs @ qkv_w^T + b
__device__ float g_q[S_TOK * DIM];      // roped Q
__device__ float g_k[S_TOK * DIM];      // roped K
__device__ float g_attn[S_TOK * DIM];   // attention output

// ---------------------------------------------------------------------------
// tf32 helpers (baseline PTX, no arch-specific features)
// ---------------------------------------------------------------------------
__device__ __forceinline__ uint32_t f2tf32(float x) {
    uint32_t r;
    asm("cvt.rna.tf32.f32 %0, %1;" : "=r"(r) : "f"(x));
    return r;
}

__device__ __forceinline__ void mma_tf32(float* c, const uint32_t* a, const uint32_t* b) {
    asm volatile(
        "mma.sync.aligned.m16n8k8.row.col.f32.tf32.tf32.f32 "
        "{%0,%1,%2,%3}, {%4,%5,%6,%7}, {%8,%9}, {%0,%1,%2,%3};"
        : "+f"(c[0]), "+f"(c[1]), "+f"(c[2]), "+f"(c[3])
        : "r"(a[0]), "r"(a[1]), "r"(a[2]), "r"(a[3]), "r"(b[0]), "r"(b[1]));
}

// ---------------------------------------------------------------------------
// tf32 tensor-core GEMM (NT): C[M,N] = A[M,K] @ B[N,K]^T + bias[N]
// BM=BN=128, BK=16, 256 threads = 8 warps (2 M x 4 N), warp tile 64x32.
// ---------------------------------------------------------------------------
#define GLD 20

__global__ __launch_bounds__(256) void gemm_tf32_mma(
    const float* __restrict__ A, const float* __restrict__ B,
    const float* __restrict__ bias, float* __restrict__ C,
    int N, int K)
{
    __shared__ uint32_t As[2][128][GLD];
    __shared__ uint32_t Bs[2][128][GLD];

    const int tid = threadIdx.x;
    const int lane = tid & 31;
    const int wid = tid >> 5;
    const int wm = (wid & 1) * 64;
    const int wn = (wid >> 1) * 32;
    const int bm = blockIdx.y * 128;
    const int bn = blockIdx.x * 128;

    const int lrow = tid >> 1;
    const int lhalf = (tid & 1) * 8;
    const float* Ag = A + (size_t)(bm + lrow) * K + lhalf;
    const float* Bg = B + (size_t)(bn + lrow) * K + lhalf;

    float acc[4][4][4];
#pragma unroll
    for (int i = 0; i < 4; i++)
#pragma unroll
        for (int j = 0; j < 4; j++)
#pragma unroll
            for (int c = 0; c < 4; c++) acc[i][j][c] = 0.f;

#define STS_TILE(buf, va0, va1, vb0, vb1) do {                               \
    uint4 _ua, _ub;                                                          \
    _ua.x = f2tf32((va0).x); _ua.y = f2tf32((va0).y);                        \
    _ua.z = f2tf32((va0).z); _ua.w = f2tf32((va0).w);                        \
    *(uint4*)&As[buf][lrow][lhalf] = _ua;                                    \
    _ua.x = f2tf32((va1).x); _ua.y = f2tf32((va1).y);                        \
    _ua.z = f2tf32((va1).z); _ua.w = f2tf32((va1).w);                        \
    *(uint4*)&As[buf][lrow][lhalf + 4] = _ua;                                \
    _ub.x = f2tf32((vb0).x); _ub.y = f2tf32((vb0).y);                        \
    _ub.z = f2tf32((vb0).z); _ub.w = f2tf32((vb0).w);                        \
    *(uint4*)&Bs[buf][lrow][lhalf] = _ub;                                    \
    _ub.x = f2tf32((vb1).x); _ub.y = f2tf32((vb1).y);                        \
    _ub.z = f2tf32((vb1).z); _ub.w = f2tf32((vb1).w);                        \
    *(uint4*)&Bs[buf][lrow][lhalf + 4] = _ub;                                \
} while (0)

    {
        float4 a0 = *(const float4*)(Ag);
        float4 a1 = *(const float4*)(Ag + 4);
        float4 b0 = *(const float4*)(Bg);
        float4 b1 = *(const float4*)(Bg + 4);
        STS_TILE(0, a0, a1, b0, b1);
    }
    __syncthreads();

    const int NT = K / 16;
    const int r = lane >> 2;
    const int cq = lane & 3;

    for (int kt = 0; kt < NT; ++kt) {
        const int buf = kt & 1;
        float4 na0, na1, nb0, nb1;
        const bool more = (kt + 1 < NT);
        if (more) {
            const float* Ap = Ag + (kt + 1) * 16;
            const float* Bp = Bg + (kt + 1) * 16;
            na0 = *(const float4*)(Ap);
            na1 = *(const float4*)(Ap + 4);
            nb0 = *(const float4*)(Bp);
            nb1 = *(const float4*)(Bp + 4);
        }

#pragma unroll
        for (int ks = 0; ks < 2; ++ks) {
            const int kc = ks * 8 + cq;
            uint32_t af[4][4], bf[4][2];
#pragma unroll
            for (int i = 0; i < 4; i++) {
                af[i][0] = As[buf][wm + i * 16 + r][kc];
                af[i][1] = As[buf][wm + i * 16 + r + 8][kc];
                af[i][2] = As[buf][wm + i * 16 + r][kc + 4];
                af[i][3] = As[buf][wm + i * 16 + r + 8][kc + 4];
            }
#pragma unroll
            for (int j = 0; j < 4; j++) {
                bf[j][0] = Bs[buf][wn + j * 8 + r][kc];
                bf[j][1] = Bs[buf][wn + j * 8 + r][kc + 4];
            }
#pragma unroll
            for (int i = 0; i < 4; i++)
#pragma unroll
                for (int j = 0; j < 4; j++)
                    mma_tf32(acc[i][j], af[i], bf[j]);
        }

        if (more) {
            STS_TILE(buf ^ 1, na0, na1, nb0, nb1);
        }
        __syncthreads();
    }
#undef STS_TILE

#pragma unroll
    for (int i = 0; i < 4; i++) {
        const int row0 = bm + wm + i * 16 + r;
#pragma unroll
        for (int j = 0; j < 4; j++) {
            const int col = bn + wn + j * 8 + cq * 2;
            const float b0 = bias[col], b1 = bias[col + 1];
            float2 v;
            v.x = acc[i][j][0] + b0;
            v.y = acc[i][j][1] + b1;
            *(float2*)(C + (size_t)row0 * N + col) = v;
            v.x = acc[i][j][2] + b0;
            v.y = acc[i][j][3] + b1;
            *(float2*)(C + (size_t)(row0 + 8) * N + col) = v;
        }
    }
}

// ---------------------------------------------------------------------------
// RoPE: q/k <- q*cos + rotate_half(q)*sin.
// ---------------------------------------------------------------------------
__global__ void rope_kernel(const float* __restrict__ cosp,
                            const float* __restrict__ sinp)
{
    int idx = blockIdx.x * blockDim.x + threadIdx.x;
    if (idx >= S_TOK * DIM) return;
    int s = idx / DIM;
    int c = idx - s * DIM;
    int d = c % DH;
    float cv = cosp[s * DH + d];
    float sv = sinp[s * DH + d];
    const float* row = g_qkv + (size_t)s * DIM3;
    float qv = row[c];
    float kv = row[DIM + c];
    float qr, kr;
    if (d < DH / 2) {
        qr = -row[c + DH / 2];
        kr = -row[DIM + c + DH / 2];
    } else {
        qr = row[c - DH / 2];
        kr = row[DIM + c - DH / 2];
    }
    g_q[idx] = fmaf(qv, cv, qr * sv);
    g_k[idx] = fmaf(kv, cv, kr * sv);
}

// ---------------------------------------------------------------------------
// Tensor-core flash attention (tf32 mma, fp32 accumulate).
// Block: 128 Q rows for one (seg, head); 8 warps x 16 rows.
// Loop over 16 KV tiles of 64. K/V staged in smem pre-converted to tf32.
// S C-frags -> softmax -> shuffle-permute to A-frags -> PV mma.
// ---------------------------------------------------------------------------
#define KS_LD 84   // row stride (uint32) for K smem: banks 20r+c, conflict-free
#define VS_LD 88   // row stride for V smem: banks 24*cq + r, conflict-free

__global__ __launch_bounds__(256, 1) void attn_mma()
{
    __shared__ uint32_t Ks[64 * KS_LD];
    __shared__ uint32_t Vs[64 * VS_LD];

    const int tid = threadIdx.x;
    const int lane = tid & 31;
    const int w = tid >> 5;
    const int r = lane >> 2;
    const int cq = lane & 3;

    const int qb = blockIdx.x;
    const int h = blockIdx.y;
    const int seg = blockIdx.z;
    const int q0 = seg * SEGLEN + qb * 128;
    const int qrow = q0 + w * 16;
    const int hoff = h * DH;
    const float scale = 0.11180339887498949f; // 1/sqrt(80)

    // Preload Q fragments (scale folded in), 10 k-slices of 8.
    uint32_t qa[10][4];
    {
        const float* Qb = g_q + (size_t)qrow * DIM + hoff;
#pragma unroll
        for (int ks = 0; ks < 10; ks++) {
            qa[ks][0] = f2tf32(Qb[(size_t)r * DIM + ks * 8 + cq] * scale);
            qa[ks][1] = f2tf32(Qb[(size_t)(r + 8) * DIM + ks * 8 + cq] * scale);
            qa[ks][2] = f2tf32(Qb[(size_t)r * DIM + ks * 8 + cq + 4] * scale);
            qa[ks][3] = f2tf32(Qb[(size_t)(r + 8) * DIM + ks * 8 + cq + 4] * scale);
        }
    }

    float m0 = -1e30f, m1 = -1e30f, l0 = 0.f, l1 = 0.f;
    float oacc[10][4];
#pragma unroll
    for (int v = 0; v < 10; v++)
#pragma unroll
        for (int c = 0; c < 4; c++) oacc[v][c] = 0.f;

    // smem fill mapping: thread -> (row = tid>>2, 20 cols at (tid&3)*20)
    const int srow = tid >> 2;
    const int scol = (tid & 3) * 20;

    for (int kvt = 0; kvt < 16; kvt++) {
        __syncthreads();
        {
            const int tok = seg * SEGLEN + kvt * 64 + srow;
            const float* kp = g_k + (size_t)tok * DIM + hoff + scol;
            const float* vp = g_qkv + (size_t)tok * DIM3 + 2 * DIM + hoff + scol;
            uint32_t* kd = &Ks[srow * KS_LD + scol];
            uint32_t* vd = &Vs[srow * VS_LD + scol];
#pragma unroll
            for (int i = 0; i < 5; i++) {
                float4 k4 = *(const float4*)(kp + i * 4);
                float4 v4 = *(const float4*)(vp + i * 4);
                uint4 uk, uv;
                uk.x = f2tf32(k4.x); uk.y = f2tf32(k4.y);
                uk.z = f2tf32(k4.z); uk.w = f2tf32(k4.w);
                uv.x = f2tf32(v4.x); uv.y = f2tf32(v4.y);
                uv.z = f2tf32(v4.z); uv.w = f2tf32(v4.w);
                *(uint4*)(kd + i * 4) = uk;
                *(uint4*)(vd + i * 4) = uv;
            }
        }
        __syncthreads();

        // S = Q K^T : 8 n-tiles of 8 kv tokens
        float sc[8][4];
#pragma unroll
        for (int j = 0; j < 8; j++)
#pragma unroll
            for (int c = 0; c < 4; c++) sc[j][c] = 0.f;

#pragma unroll
        for (int ks = 0; ks < 10; ks++) {
#pragma unroll
            for (int j = 0; j < 8; j++) {
                uint32_t b[2];
                b[0] = Ks[(j * 8 + r) * KS_LD + ks * 8 + cq];
                b[1] = Ks[(j * 8 + r) * KS_LD + ks * 8 + cq + 4];
                mma_tf32(sc[j], qa[ks], b);
            }
        }

        // Online softmax. Row r: sc[j][0..1]; row r+8: sc[j][2..3].
        float mx0 = -1e30f, mx1 = -1e30f;
#pragma unroll
        for (int j = 0; j < 8; j++) {
            mx0 = fmaxf(mx0, fmaxf(sc[j][0], sc[j][1]));
            mx1 = fmaxf(mx1, fmaxf(sc[j][2], sc[j][3]));
        }
        mx0 = fmaxf(mx0, __shfl_xor_sync(0xffffffffu, mx0, 1));
        mx0 = fmaxf(mx0, __shfl_xor_sync(0xffffffffu, mx0, 2));
        mx1 = fmaxf(mx1, __shfl_xor_sync(0xffffffffu, mx1, 1));
        mx1 = fmaxf(mx1, __shfl_xor_sync(0xffffffffu, mx1, 2));
        const float nm0 = fmaxf(m0, mx0);
        const float nm1 = fmaxf(m1, mx1);
        const float corr0 = __expf(m0 - nm0);
        const float corr1 = __expf(m1 - nm1);
        m0 = nm0; m1 = nm1;

        float sum0 = 0.f, sum1 = 0.f;
#pragma unroll
        for (int j = 0; j < 8; j++) {
            sc[j][0] = __expf(sc[j][0] - nm0);
            sc[j][1] = __expf(sc[j][1] - nm0);
            sc[j][2] = __expf(sc[j][2] - nm1);
            sc[j][3] = __expf(sc[j][3] - nm1);
            sum0 += sc[j][0] + sc[j][1];
            sum1 += sc[j][2] + sc[j][3];
        }
        sum0 += __shfl_xor_sync(0xffffffffu, sum0, 1);
        sum0 += __shfl_xor_sync(0xffffffffu, sum0, 2);
        sum1 += __shfl_xor_sync(0xffffffffu, sum1, 1);
        sum1 += __shfl_xor_sync(0xffffffffu, sum1, 2);
        l0 = l0 * corr0 + sum0;
        l1 = l1 * corr1 + sum1;

#pragma unroll
        for (int v = 0; v < 10; v++) {
            oacc[v][0] *= corr0; oacc[v][1] *= corr0;
            oacc[v][2] *= corr1; oacc[v][3] *= corr1;
        }

        // P C-frag -> A-frag (shuffle permutation), then O += P V
        const int srcA = r * 4 + (cq >> 1);
        const int srcB = srcA + 2;
        const bool odd = cq & 1;
#pragma unroll
        for (int s = 0; s < 8; s++) {
            float x0 = __shfl_sync(0xffffffffu, sc[s][0], srcA);
            float x1 = __shfl_sync(0xffffffffu, sc[s][1], srcA);
            float y0 = __shfl_sync(0xffffffffu, sc[s][2], srcA);
            float y1 = __shfl_sync(0xffffffffu, sc[s][3], srcA);
            float z0 = __shfl_sync(0xffffffffu, sc[s][0], srcB);
            float z1 = __shfl_sync(0xffffffffu, sc[s][1], srcB);
            float u0 = __shfl_sync(0xffffffffu, sc[s][2], srcB);
            float u1 = __shfl_sync(0xffffffffu, sc[s][3], srcB);
            uint32_t pa[4];
            pa[0] = f2tf32(odd ? x1 : x0);
            pa[1] = f2tf32(odd ? y1 : y0);
            pa[2] = f2tf32(odd ? z1 : z0);
            pa[3] = f2tf32(odd ? u1 : u0);
#pragma unroll
            for (int v = 0; v < 10; v++) {
                uint32_t b[2];
                b[0] = Vs[(s * 8 + cq) * VS_LD + v * 8 + r];
                b[1] = Vs[(s * 8 + cq + 4) * VS_LD + v * 8 + r];
                mma_tf32(oacc[v], pa, b);
            }
        }
    }

    // Epilogue
    const float inv0 = 1.f / l0;
    const float inv1 = 1.f / l1;
    float* O0 = g_attn + (size_t)(qrow + r) * DIM + hoff;
    float* O1 = g_attn + (size_t)(qrow + r + 8) * DIM + hoff;
#pragma unroll
    for (int v = 0; v < 10; v++) {
        float2 o;
        o.x = oacc[v][0] * inv0;
        o.y = oacc[v][1] * inv0;
        *(float2*)(O0 + v * 8 + 2 * cq) = o;
        o.x = oacc[v][2] * inv1;
        o.y = oacc[v][3] * inv1;
        *(float2*)(O1 + v * 8 + 2 * cq) = o;
    }
}

// ---------------------------------------------------------------------------
extern "C" void kernel_launch(void* const* d_in, const int* in_sizes, int n_in,
                              void* d_out, int out_size)
{
    const float* hs     = (const float*)d_in[0];
    const float* cosp   = (const float*)d_in[1];
    const float* sinp   = (const float*)d_in[2];
    const float* qkv_w  = (const float*)d_in[3];
    const float* qkv_b  = (const float*)d_in[4];
    const float* proj_w = (const float*)d_in[5];
    const float* proj_b = (const float*)d_in[6];
    float* out = (float*)d_out;

    float *qkv_ptr, *attn_ptr;
    cudaGetSymbolAddress((void**)&qkv_ptr, g_qkv);
    cudaGetSymbolAddress((void**)&attn_ptr, g_attn);

    // 1) QKV GEMM + bias (tf32 tensor cores)
    dim3 g1(DIM3 / 128, S_TOK / 128);
    gemm_tf32_mma<<<g1, 256>>>(hs, qkv_w, qkv_b, qkv_ptr, DIM3, DIM);

    // 2) RoPE on Q,K
    int total = S_TOK * DIM;
    rope_kernel<<<(total + 255) / 256, 256>>>(cosp, sinp);

    // 3) Tensor-core flash attention
    dim3 g2(SEGLEN / 128, NH, NSEG);
    attn_mma<<<g2, 256>>>();

    // 4) Output projection + bias (tf32 tensor cores)
    dim3 g3(DIM / 128, S_TOK / 128);
    gemm_tf32_mma<<<g3, 256>>>(attn_ptr, proj_w, proj_b, out, DIM, DIM);
}

// round 7
// speedup vs baseline: 3.0262x; 1.1007x over previous
#include <cuda_runtime.h>
#include <cstdint>
#include <cstddef>

#define S_TOK 8192
#define DIM 1280
#define DIM3 3840
#define NH 16
#define DH 80
#define NSEG 8
#define SEGLEN 1024

// Scratch (device globals: allocation-free per harness rules)
__device__ float g_qkv[S_TOK * DIM3];   // raw qkv = hs @ qkv_w^T + b
__device__ float g_q[S_TOK * DIM];      // roped Q
__device__ float g_k[S_TOK * DIM];      // roped K
__device__ float g_attn[S_TOK * DIM];   // attention output

// ---------------------------------------------------------------------------
// tf32 helpers (baseline PTX, no arch-specific features)
// ---------------------------------------------------------------------------
__device__ __forceinline__ uint32_t f2tf32(float x) {
    uint32_t r;
    asm("cvt.rna.tf32.f32 %0, %1;" : "=r"(r) : "f"(x));
    return r;
}

__device__ __forceinline__ void mma_tf32(float* c, const uint32_t* a, const uint32_t* b) {
    asm volatile(
        "mma.sync.aligned.m16n8k8.row.col.f32.tf32.tf32.f32 "
        "{%0,%1,%2,%3}, {%4,%5,%6,%7}, {%8,%9}, {%0,%1,%2,%3};"
        : "+f"(c[0]), "+f"(c[1]), "+f"(c[2]), "+f"(c[3])
        : "r"(a[0]), "r"(a[1]), "r"(a[2]), "r"(a[3]), "r"(b[0]), "r"(b[1]));
}

__device__ __forceinline__ void ldsm_x4(uint32_t* r, uint32_t addr) {
    asm volatile(
        "ldmatrix.sync.aligned.m8n8.x4.shared.b16 {%0,%1,%2,%3}, [%4];"
        : "=r"(r[0]), "=r"(r[1]), "=r"(r[2]), "=r"(r[3]) : "r"(addr));
}

__device__ __forceinline__ uint32_t smem_addr_u32(const void* p) {
    return (uint32_t)__cvta_generic_to_shared(p);
}

// ---------------------------------------------------------------------------
// tf32 tensor-core GEMM (NT): C[M,N] = A[M,K] @ B[N,K]^T + bias[N]
// BM=BN=128, BK=16, 256 threads = 8 warps (2 M x 4 N), warp tile 64x32.
// Fragment loads via ldmatrix (4 A-LDSM.x4 + 2 B-LDSM.x4 per k-slice).
// ---------------------------------------------------------------------------
#define GLD 20

__global__ __launch_bounds__(256) void gemm_tf32_mma(
    const float* __restrict__ A, const float* __restrict__ B,
    const float* __restrict__ bias, float* __restrict__ C,
    int N, int K)
{
    __shared__ uint32_t As[2][128][GLD];
    __shared__ uint32_t Bs[2][128][GLD];

    const int tid = threadIdx.x;
    const int lane = tid & 31;
    const int wid = tid >> 5;
    const int wm = (wid & 1) * 64;
    const int wn = (wid >> 1) * 32;
    const int bm = blockIdx.y * 128;
    const int bn = blockIdx.x * 128;

    const int lrow = tid >> 1;
    const int lhalf = (tid & 1) * 8;
    const float* Ag = A + (size_t)(bm + lrow) * K + lhalf;
    const float* Bg = B + (size_t)(bn + lrow) * K + lhalf;

    // ldmatrix per-lane element offsets (in uint32 units) within a buffer
    //   A x4 (matrices: rows0-7/kc, rows8-15/kc, rows0-7/kc+4, rows8-15/kc+4)
    const int a_off = (wm + (lane & 15)) * GLD + ((lane >> 4) << 2);
    //   B x4 (matrices: j rows/kc, j rows/kc+4, j+1 rows/kc, j+1 rows/kc+4)
    const int b_off = (wn + (lane & 7) + ((lane >> 4) << 3)) * GLD +
                      (((lane >> 3) & 1) << 2);

    const uint32_t As_base = smem_addr_u32(&As[0][0][0]);
    const uint32_t Bs_base = smem_addr_u32(&Bs[0][0][0]);
    const uint32_t buf_stride = 128 * GLD * 4;

    float acc[4][4][4];
#pragma unroll
    for (int i = 0; i < 4; i++)
#pragma unroll
        for (int j = 0; j < 4; j++)
#pragma unroll
            for (int c = 0; c < 4; c++) acc[i][j][c] = 0.f;

#define STS_TILE(buf, va0, va1, vb0, vb1) do {                               \
    uint4 _ua, _ub;                                                          \
    _ua.x = f2tf32((va0).x); _ua.y = f2tf32((va0).y);                        \
    _ua.z = f2tf32((va0).z); _ua.w = f2tf32((va0).w);                        \
    *(uint4*)&As[buf][lrow][lhalf] = _ua;                                    \
    _ua.x = f2tf32((va1).x); _ua.y = f2tf32((va1).y);                        \
    _ua.z = f2tf32((va1).z); _ua.w = f2tf32((va1).w);                        \
    *(uint4*)&As[buf][lrow][lhalf + 4] = _ua;                                \
    _ub.x = f2tf32((vb0).x); _ub.y = f2tf32((vb0).y);                        \
    _ub.z = f2tf32((vb0).z); _ub.w = f2tf32((vb0).w);                        \
    *(uint4*)&Bs[buf][lrow][lhalf] = _ub;                                    \
    _ub.x = f2tf32((vb1).x); _ub.y = f2tf32((vb1).y);                        \
    _ub.z = f2tf32((vb1).z); _ub.w = f2tf32((vb1).w);                        \
    *(uint4*)&Bs[buf][lrow][lhalf + 4] = _ub;                                \
} while (0)

    {
        float4 a0 = *(const float4*)(Ag);
        float4 a1 = *(const float4*)(Ag + 4);
        float4 b0 = *(const float4*)(Bg);
        float4 b1 = *(const float4*)(Bg + 4);
        STS_TILE(0, a0, a1, b0, b1);
    }
    __syncthreads();

    const int NT = K / 16;
    const int r = lane >> 2;
    const int cq = lane & 3;

    for (int kt = 0; kt < NT; ++kt) {
        const int buf = kt & 1;
        float4 na0, na1, nb0, nb1;
        const bool more = (kt + 1 < NT);
        if (more) {
            const float* Ap = Ag + (kt + 1) * 16;
            const float* Bp = Bg + (kt + 1) * 16;
            na0 = *(const float4*)(Ap);
            na1 = *(const float4*)(Ap + 4);
            nb0 = *(const float4*)(Bp);
            nb1 = *(const float4*)(Bp + 4);
        }

        const uint32_t a_base = As_base + buf * buf_stride + a_off * 4;
        const uint32_t b_base = Bs_base + buf * buf_stride + b_off * 4;

#pragma unroll
        for (int ks = 0; ks < 2; ++ks) {
            const uint32_t kcb = ks * 8 * 4;   // byte offset of k-slice
            uint32_t af[4][4], bq[2][4];
#pragma unroll
            for (int i = 0; i < 4; i++)
                ldsm_x4(af[i], a_base + (uint32_t)(i * 16 * GLD * 4) + kcb);
#pragma unroll
            for (int jp = 0; jp < 2; jp++)
                ldsm_x4(bq[jp], b_base + (uint32_t)(jp * 16 * GLD * 4) + kcb);
#pragma unroll
            for (int i = 0; i < 4; i++)
#pragma unroll
                for (int j = 0; j < 4; j++)
                    mma_tf32(acc[i][j], af[i], &bq[j >> 1][(j & 1) * 2]);
        }

        if (more) {
            STS_TILE(buf ^ 1, na0, na1, nb0, nb1);
        }
        __syncthreads();
    }
#undef STS_TILE

#pragma unroll
    for (int i = 0; i < 4; i++) {
        const int row0 = bm + wm + i * 16 + r;
#pragma unroll
        for (int j = 0; j < 4; j++) {
            const int col = bn + wn + j * 8 + cq * 2;
            const float b0 = bias[col], b1 = bias[col + 1];
            float2 v;
            v.x = acc[i][j][0] + b0;
            v.y = acc[i][j][1] + b1;
            *(float2*)(C + (size_t)row0 * N + col) = v;
            v.x = acc[i][j][2] + b0;
            v.y = acc[i][j][3] + b1;
            *(float2*)(C + (size_t)(row0 + 8) * N + col) = v;
        }
    }
}

// ---------------------------------------------------------------------------
// RoPE: q/k <- q*cos + rotate_half(q)*sin.
// ---------------------------------------------------------------------------
__global__ void rope_kernel(const float* __restrict__ cosp,
                            const float* __restrict__ sinp)
{
    int idx = blockIdx.x * blockDim.x + threadIdx.x;
    if (idx >= S_TOK * DIM) return;
    int s = idx / DIM;
    int c = idx - s * DIM;
    int d = c % DH;
    float cv = cosp[s * DH + d];
    float sv = sinp[s * DH + d];
    const float* row = g_qkv + (size_t)s * DIM3;
    float qv = row[c];
    float kv = row[DIM + c];
    float qr, kr;
    if (d < DH / 2) {
        qr = -row[c + DH / 2];
        kr = -row[DIM + c + DH / 2];
    } else {
        qr = row[c - DH / 2];
        kr = row[DIM + c - DH / 2];
    }
    g_q[idx] = fmaf(qv, cv, qr * sv);
    g_k[idx] = fmaf(kv, cv, kr * sv);
}

// ---------------------------------------------------------------------------
// Tensor-core flash attention (tf32 mma, fp32 accumulate).
// Block: 128 Q rows for one (seg, head); 8 warps x 16 rows.
// ---------------------------------------------------------------------------
#define KS_LD 84
#define VS_LD 88

__global__ __launch_bounds__(256, 1) void attn_mma()
{
    __shared__ uint32_t Ks[64 * KS_LD];
    __shared__ uint32_t Vs[64 * VS_LD];

    const int tid = threadIdx.x;
    const int lane = tid & 31;
    const int w = tid >> 5;
    const int r = lane >> 2;
    const int cq = lane & 3;

    const int qb = blockIdx.x;
    const int h = blockIdx.y;
    const int seg = blockIdx.z;
    const int q0 = seg * SEGLEN + qb * 128;
    const int qrow = q0 + w * 16;
    const int hoff = h * DH;
    const float scale = 0.11180339887498949f; // 1/sqrt(80)

    uint32_t qa[10][4];
    {
        const float* Qb = g_q + (size_t)qrow * DIM + hoff;
#pragma unroll
        for (int ks = 0; ks < 10; ks++) {
            qa[ks][0] = f2tf32(Qb[(size_t)r * DIM + ks * 8 + cq] * scale);
            qa[ks][1] = f2tf32(Qb[(size_t)(r + 8) * DIM + ks * 8 + cq] * scale);
            qa[ks][2] = f2tf32(Qb[(size_t)r * DIM + ks * 8 + cq + 4] * scale);
            qa[ks][3] = f2tf32(Qb[(size_t)(r + 8) * DIM + ks * 8 + cq + 4] * scale);
        }
    }

    float m0 = -1e30f, m1 = -1e30f, l0 = 0.f, l1 = 0.f;
    float oacc[10][4];
#pragma unroll
    for (int v = 0; v < 10; v++)
#pragma unroll
        for (int c = 0; c < 4; c++) oacc[v][c] = 0.f;

    const int srow = tid >> 2;
    const int scol = (tid & 3) * 20;

    for (int kvt = 0; kvt < 16; kvt++) {
        __syncthreads();
        {
            const int tok = seg * SEGLEN + kvt * 64 + srow;
            const float* kp = g_k + (size_t)tok * DIM + hoff + scol;
            const float* vp = g_qkv + (size_t)tok * DIM3 + 2 * DIM + hoff + scol;
            uint32_t* kd = &Ks[srow * KS_LD + scol];
            uint32_t* vd = &Vs[srow * VS_LD + scol];
#pragma unroll
            for (int i = 0; i < 5; i++) {
                float4 k4 = *(const float4*)(kp + i * 4);
                float4 v4 = *(const float4*)(vp + i * 4);
                uint4 uk, uv;
                uk.x = f2tf32(k4.x); uk.y = f2tf32(k4.y);
                uk.z = f2tf32(k4.z); uk.w = f2tf32(k4.w);
                uv.x = f2tf32(v4.x); uv.y = f2tf32(v4.y);
                uv.z = f2tf32(v4.z); uv.w = f2tf32(v4.w);
                *(uint4*)(kd + i * 4) = uk;
                *(uint4*)(vd + i * 4) = uv;
            }
        }
        __syncthreads();

        float sc[8][4];
#pragma unroll
        for (int j = 0; j < 8; j++)
#pragma unroll
            for (int c = 0; c < 4; c++) sc[j][c] = 0.f;

#pragma unroll
        for (int ks = 0; ks < 10; ks++) {
#pragma unroll
            for (int j = 0; j < 8; j++) {
                uint32_t b[2];
                b[0] = Ks[(j * 8 + r) * KS_LD + ks * 8 + cq];
                b[1] = Ks[(j * 8 + r) * KS_LD + ks * 8 + cq + 4];
                mma_tf32(sc[j], qa[ks], b);
            }
        }

        float mx0 = -1e30f, mx1 = -1e30f;
#pragma unroll
        for (int j = 0; j < 8; j++) {
            mx0 = fmaxf(mx0, fmaxf(sc[j][0], sc[j][1]));
            mx1 = fmaxf(mx1, fmaxf(sc[j][2], sc[j][3]));
        }
        mx0 = fmaxf(mx0, __shfl_xor_sync(0xffffffffu, mx0, 1));
        mx0 = fmaxf(mx0, __shfl_xor_sync(0xffffffffu, mx0, 2));
        mx1 = fmaxf(mx1, __shfl_xor_sync(0xffffffffu, mx1, 1));
        mx1 = fmaxf(mx1, __shfl_xor_sync(0xffffffffu, mx1, 2));
        const float nm0 = fmaxf(m0, mx0);
        const float nm1 = fmaxf(m1, mx1);
        const float corr0 = __expf(m0 - nm0);
        const float corr1 = __expf(m1 - nm1);
        m0 = nm0; m1 = nm1;

        float sum0 = 0.f, sum1 = 0.f;
#pragma unroll
        for (int j = 0; j < 8; j++) {
            sc[j][0] = __expf(sc[j][0] - nm0);
            sc[j][1] = __expf(sc[j][1] - nm0);
            sc[j][2] = __expf(sc[j][2] - nm1);
            sc[j][3] = __expf(sc[j][3] - nm1);
            sum0 += sc[j][0] + sc[j][1];
            sum1 += sc[j][2] + sc[j][3];
        }
        sum0 += __shfl_xor_sync(0xffffffffu, sum0, 1);
        sum0 += __shfl_xor_sync(0xffffffffu, sum0, 2);
        sum1 += __shfl_xor_sync(0xffffffffu, sum1, 1);
        sum1 += __shfl_xor_sync(0xffffffffu, sum1, 2);
        l0 = l0 * corr0 + sum0;
        l1 = l1 * corr1 + sum1;

#pragma unroll
        for (int v = 0; v < 10; v++) {
            oacc[v][0] *= corr0; oacc[v][1] *= corr0;
            oacc[v][2] *= corr1; oacc[v][3] *= corr1;
        }

        const int srcA = r * 4 + (cq >> 1);
        const int srcB = srcA + 2;
        const bool odd = cq & 1;
#pragma unroll
        for (int s = 0; s < 8; s++) {
            float x0 = __shfl_sync(0xffffffffu, sc[s][0], srcA);
            float x1 = __shfl_sync(0xffffffffu, sc[s][1], srcA);
            float y0 = __shfl_sync(0xffffffffu, sc[s][2], srcA);
            float y1 = __shfl_sync(0xffffffffu, sc[s][3], srcA);
            float z0 = __shfl_sync(0xffffffffu, sc[s][0], srcB);
            float z1 = __shfl_sync(0xffffffffu, sc[s][1], srcB);
            float u0 = __shfl_sync(0xffffffffu, sc[s][2], srcB);
            float u1 = __shfl_sync(0xffffffffu, sc[s][3], srcB);
            uint32_t pa[4];
            pa[0] = f2tf32(odd ? x1 : x0);
            pa[1] = f2tf32(odd ? y1 : y0);
            pa[2] = f2tf32(odd ? z1 : z0);
            pa[3] = f2tf32(odd ? u1 : u0);
#pragma unroll
            for (int v = 0; v < 10; v++) {
                uint32_t b[2];
                b[0] = Vs[(s * 8 + cq) * VS_LD + v * 8 + r];
                b[1] = Vs[(s * 8 + cq + 4) * VS_LD + v * 8 + r];
                mma_tf32(oacc[v], pa, b);
            }
        }
    }

    const float inv0 = 1.f / l0;
    const float inv1 = 1.f / l1;
    float* O0 = g_attn + (size_t)(qrow + r) * DIM + hoff;
    float* O1 = g_attn + (size_t)(qrow + r + 8) * DIM + hoff;
#pragma unroll
    for (int v = 0; v < 10; v++) {
        float2 o;
        o.x = oacc[v][0] * inv0;
        o.y = oacc[v][1] * inv0;
        *(float2*)(O0 + v * 8 + 2 * cq) = o;
        o.x = oacc[v][2] * inv1;
        o.y = oacc[v][3] * inv1;
        *(float2*)(O1 + v * 8 + 2 * cq) = o;
    }
}

// ---------------------------------------------------------------------------
extern "C" void kernel_launch(void* const* d_in, const int* in_sizes, int n_in,
                              void* d_out, int out_size)
{
    const float* hs     = (const float*)d_in[0];
    const float* cosp   = (const float*)d_in[1];
    const float* sinp   = (const float*)d_in[2];
    const float* qkv_w  = (const float*)d_in[3];
    const float* qkv_b  = (const float*)d_in[4];
    const float* proj_w = (const float*)d_in[5];
    const float* proj_b = (const float*)d_in[6];
    float* out = (float*)d_out;

    float *qkv_ptr, *attn_ptr;
    cudaGetSymbolAddress((void**)&qkv_ptr, g_qkv);
    cudaGetSymbolAddress((void**)&attn_ptr, g_attn);

    // 1) QKV GEMM + bias (tf32 tensor cores, ldmatrix)
    dim3 g1(DIM3 / 128, S_TOK / 128);
    gemm_tf32_mma<<<g1, 256>>>(hs, qkv_w, qkv_b, qkv_ptr, DIM3, DIM);

    // 2) RoPE on Q,K
    int total = S_TOK * DIM;
    rope_kernel<<<(total + 255) / 256, 256>>>(cosp, sinp);

    // 3) Tensor-core flash attention
    dim3 g2(SEGLEN / 128, NH, NSEG);
    attn_mma<<<g2, 256>>>();

    // 4) Output projection + bias (tf32 tensor cores, ldmatrix)
    dim3 g3(DIM / 128, S_TOK / 128);
    gemm_tf32_mma<<<g3, 256>>>(attn_ptr, proj_w, proj_b, out, DIM, DIM);
}

// round 8
// speedup vs baseline: 3.4077x; 1.1261x over previous
#include <cuda_runtime.h>
#include <cstdint>
#include <cstddef>

#define S_TOK 8192
#define DIM 1280
#define DIM3 3840
#define NH 16
#define DH 80
#define NSEG 8
#define SEGLEN 1024
#define GK 1280          // GEMM K (both GEMMs)
#define GNT (GK / 16)    // 80 k-tiles

// Scratch (device globals: allocation-free per harness rules)
__device__ float g_qkv[S_TOK * DIM3];   // qkv = hs @ qkv_w^T + b (tf32-rounded)
__device__ float g_q[S_TOK * DIM];      // roped Q * scale (tf32-rounded)
__device__ float g_k[S_TOK * DIM];      // roped K (tf32-rounded)
__device__ float g_attn[S_TOK * DIM];   // attention out (tf32-rounded)
__device__ float g_hs[S_TOK * DIM];     // tf32-rounded hidden_states
__device__ float g_wq[DIM3 * DIM];      // tf32-rounded qkv_w
__device__ float g_wp[DIM * DIM];       // tf32-rounded proj_w

// ---------------------------------------------------------------------------
// tf32 helpers (baseline PTX, no arch-specific features)
// ---------------------------------------------------------------------------
__device__ __forceinline__ uint32_t f2tf32(float x) {
    uint32_t r;
    asm("cvt.rna.tf32.f32 %0, %1;" : "=r"(r) : "f"(x));
    return r;
}

__device__ __forceinline__ void mma_tf32(float* c, const uint32_t* a, const uint32_t* b) {
    asm volatile(
        "mma.sync.aligned.m16n8k8.row.col.f32.tf32.tf32.f32 "
        "{%0,%1,%2,%3}, {%4,%5,%6,%7}, {%8,%9}, {%0,%1,%2,%3};"
        : "+f"(c[0]), "+f"(c[1]), "+f"(c[2]), "+f"(c[3])
        : "r"(a[0]), "r"(a[1]), "r"(a[2]), "r"(a[3]), "r"(b[0]), "r"(b[1]));
}

__device__ __forceinline__ void ldsm_x4(uint32_t* r, uint32_t addr) {
    asm volatile(
        "ldmatrix.sync.aligned.m8n8.x4.shared.b16 {%0,%1,%2,%3}, [%4];"
        : "=r"(r[0]), "=r"(r[1]), "=r"(r[2]), "=r"(r[3]) : "r"(addr));
}

__device__ __forceinline__ uint32_t smem_addr_u32(const void* p) {
    return (uint32_t)__cvta_generic_to_shared(p);
}

// ---------------------------------------------------------------------------
// Pre-round fp32 -> tf32-valued fp32 (vectorized)
// ---------------------------------------------------------------------------
__global__ void round_tf32_kernel(const float4* __restrict__ src,
                                  float4* __restrict__ dst, int n4)
{
    int i = blockIdx.x * blockDim.x + threadIdx.x;
    if (i >= n4) return;
    float4 v = src[i];
    float4 o;
    o.x = __uint_as_float(f2tf32(v.x));
    o.y = __uint_as_float(f2tf32(v.y));
    o.z = __uint_as_float(f2tf32(v.z));
    o.w = __uint_as_float(f2tf32(v.w));
    dst[i] = o;
}

// ---------------------------------------------------------------------------
// tf32 tensor-core GEMM (NT): C[M,N] = A[M,1280] @ B[N,1280]^T + bias[N]
// Inputs pre-rounded to tf32. BM=BN=128, BK=16, 256 threads (8 warps, 2Mx4N).
// 4-stage cp.async pipeline; fragments via ldmatrix.
// ---------------------------------------------------------------------------
#define GLD 20
#define STAGES 4
#define STAGE_U32 (128 * GLD)
#define GEMM_SMEM (STAGES * 2 * STAGE_U32 * 4)   // 81920 B

__global__ __launch_bounds__(256, 2) void gemm_tf32_pipe(
    const float* __restrict__ A, const float* __restrict__ B,
    const float* __restrict__ bias, float* __restrict__ C,
    int N, int round_out)
{
    extern __shared__ uint32_t smp[];
    uint32_t* As = smp;                        // [STAGES][128][GLD]
    uint32_t* Bs = smp + STAGES * STAGE_U32;   // [STAGES][128][GLD]

    const int tid = threadIdx.x;
    const int lane = tid & 31;
    const int wid = tid >> 5;
    const int wm = (wid & 1) * 64;
    const int wn = (wid >> 1) * 32;
    const int bm = blockIdx.y * 128;
    const int bn = blockIdx.x * 128;

    const int lrow = tid >> 1;
    const int lhalf = (tid & 1) * 8;
    const float* Ag = A + (size_t)(bm + lrow) * GK + lhalf;
    const float* Bg = B + (size_t)(bn + lrow) * GK + lhalf;

    const uint32_t As_base = smem_addr_u32(As);
    const uint32_t Bs_base = smem_addr_u32(Bs);
    const uint32_t stage_bytes = STAGE_U32 * 4;
    const uint32_t sA = As_base + (uint32_t)(lrow * GLD + lhalf) * 4;
    const uint32_t sB = Bs_base + (uint32_t)(lrow * GLD + lhalf) * 4;

    // ldmatrix per-lane offsets (uint32 units), same mapping as validated R7
    const int a_off = (wm + (lane & 15)) * GLD + ((lane >> 4) << 2);
    const int b_off = (wn + (lane & 7) + ((lane >> 4) << 3)) * GLD +
                      (((lane >> 3) & 1) << 2);

    float acc[4][4][4];
#pragma unroll
    for (int i = 0; i < 4; i++)
#pragma unroll
        for (int j = 0; j < 4; j++)
#pragma unroll
            for (int c = 0; c < 4; c++) acc[i][j][c] = 0.f;

#define ISSUE(ktv) do {                                                      \
    const int _st = (ktv) % STAGES;                                          \
    const float* _ap = Ag + (ktv) * 16;                                      \
    const float* _bp = Bg + (ktv) * 16;                                      \
    uint32_t _da = sA + _st * stage_bytes;                                   \
    uint32_t _db = sB + _st * stage_bytes;                                   \
    asm volatile(                                                            \
        "cp.async.cg.shared.global [%0], [%1], 16;\n\t"                      \
        "cp.async.cg.shared.global [%2], [%3], 16;\n\t"                      \
        "cp.async.cg.shared.global [%4], [%5], 16;\n\t"                      \
        "cp.async.cg.shared.global [%6], [%7], 16;\n\t"                      \
        "cp.async.commit_group;"                                             \
        :: "r"(_da), "l"(_ap), "r"(_da + 16), "l"(_ap + 4),                  \
           "r"(_db), "l"(_bp), "r"(_db + 16), "l"(_bp + 4) : "memory");      \
} while (0)

#pragma unroll
    for (int s = 0; s < STAGES - 1; s++) ISSUE(s);

    for (int kt = 0; kt < GNT; ++kt) {
        const int st = kt % STAGES;
        asm volatile("cp.async.wait_group %0;" :: "n"(STAGES - 2));
        __syncthreads();
        if (kt + STAGES - 1 < GNT) ISSUE(kt + STAGES - 1);

        const uint32_t a_base = As_base + st * stage_bytes + a_off * 4;
        const uint32_t b_base = Bs_base + st * stage_bytes + b_off * 4;
#pragma unroll
        for (int ks = 0; ks < 2; ++ks) {
            const uint32_t kcb = ks * 8 * 4;
            uint32_t af[4][4], bq[2][4];
#pragma unroll
            for (int i = 0; i < 4; i++)
                ldsm_x4(af[i], a_base + (uint32_t)(i * 16 * GLD * 4) + kcb);
#pragma unroll
            for (int jp = 0; jp < 2; jp++)
                ldsm_x4(bq[jp], b_base + (uint32_t)(jp * 16 * GLD * 4) + kcb);
#pragma unroll
            for (int i = 0; i < 4; i++)
#pragma unroll
                for (int j = 0; j < 4; j++)
                    mma_tf32(acc[i][j], af[i], &bq[j >> 1][(j & 1) * 2]);
        }
    }
#undef ISSUE

    const int r = lane >> 2;
    const int cq = lane & 3;
#pragma unroll
    for (int i = 0; i < 4; i++) {
        const int row0 = bm + wm + i * 16 + r;
#pragma unroll
        for (int j = 0; j < 4; j++) {
            const int col = bn + wn + j * 8 + cq * 2;
            const float b0 = bias[col], b1 = bias[col + 1];
            float2 v;
            v.x = acc[i][j][0] + b0;
            v.y = acc[i][j][1] + b1;
            if (round_out) {
                v.x = __uint_as_float(f2tf32(v.x));
                v.y = __uint_as_float(f2tf32(v.y));
            }
            *(float2*)(C + (size_t)row0 * N + col) = v;
            v.x = acc[i][j][2] + b0;
            v.y = acc[i][j][3] + b1;
            if (round_out) {
                v.x = __uint_as_float(f2tf32(v.x));
                v.y = __uint_as_float(f2tf32(v.y));
            }
            *(float2*)(C + (size_t)(row0 + 8) * N + col) = v;
        }
    }
}

// ---------------------------------------------------------------------------
// RoPE: q <- round((q*cos + rot(q)*sin) * scale), k <- round(k*cos + rot(k)*sin)
// ---------------------------------------------------------------------------
__global__ void rope_kernel(const float* __restrict__ cosp,
                            const float* __restrict__ sinp)
{
    int idx = blockIdx.x * blockDim.x + threadIdx.x;
    if (idx >= S_TOK * DIM) return;
    int s = idx / DIM;
    int c = idx - s * DIM;
    int d = c % DH;
    float cv = cosp[s * DH + d];
    float sv = sinp[s * DH + d];
    const float* row = g_qkv + (size_t)s * DIM3;
    float qv = row[c];
    float kv = row[DIM + c];
    float qr, kr;
    if (d < DH / 2) {
        qr = -row[c + DH / 2];
        kr = -row[DIM + c + DH / 2];
    } else {
        qr = row[c - DH / 2];
        kr = row[DIM + c - DH / 2];
    }
    const float scale = 0.11180339887498949f; // 1/sqrt(80)
    g_q[idx] = __uint_as_float(f2tf32(fmaf(qv, cv, qr * sv) * scale));
    g_k[idx] = __uint_as_float(f2tf32(fmaf(kv, cv, kr * sv)));
}

// ---------------------------------------------------------------------------
// Tensor-core flash attention (tf32 mma, fp32 accumulate).
// Q/K/V arrive pre-rounded to tf32: fills are raw copies, Q is bit-loaded.
// ---------------------------------------------------------------------------
#define KS_LD 84
#define VS_LD 88

__global__ __launch_bounds__(256, 1) void attn_mma()
{
    __shared__ uint32_t Ks[64 * KS_LD];
    __shared__ uint32_t Vs[64 * VS_LD];

    const int tid = threadIdx.x;
    const int lane = tid & 31;
    const int w = tid >> 5;
    const int r = lane >> 2;
    const int cq = lane & 3;

    const int qb = blockIdx.x;
    const int h = blockIdx.y;
    const int seg = blockIdx.z;
    const int q0 = seg * SEGLEN + qb * 128;
    const int qrow = q0 + w * 16;
    const int hoff = h * DH;

    uint32_t qa[10][4];
    {
        const float* Qb = g_q + (size_t)qrow * DIM + hoff;
#pragma unroll
        for (int ks = 0; ks < 10; ks++) {
            qa[ks][0] = __float_as_uint(Qb[(size_t)r * DIM + ks * 8 + cq]);
            qa[ks][1] = __float_as_uint(Qb[(size_t)(r + 8) * DIM + ks * 8 + cq]);
            qa[ks][2] = __float_as_uint(Qb[(size_t)r * DIM + ks * 8 + cq + 4]);
            qa[ks][3] = __float_as_uint(Qb[(size_t)(r + 8) * DIM + ks * 8 + cq + 4]);
        }
    }

    float m0 = -1e30f, m1 = -1e30f, l0 = 0.f, l1 = 0.f;
    float oacc[10][4];
#pragma unroll
    for (int v = 0; v < 10; v++)
#pragma unroll
        for (int c = 0; c < 4; c++) oacc[v][c] = 0.f;

    const int srow = tid >> 2;
    const int scol = (tid & 3) * 20;

    for (int kvt = 0; kvt < 16; kvt++) {
        __syncthreads();
        {
            const int tok = seg * SEGLEN + kvt * 64 + srow;
            const uint32_t* kp = (const uint32_t*)(g_k + (size_t)tok * DIM + hoff + scol);
            const uint32_t* vp = (const uint32_t*)(g_qkv + (size_t)tok * DIM3 + 2 * DIM + hoff + scol);
            uint32_t* kd = &Ks[srow * KS_LD + scol];
            uint32_t* vd = &Vs[srow * VS_LD + scol];
#pragma unroll
            for (int i = 0; i < 5; i++) {
                *(uint4*)(kd + i * 4) = *(const uint4*)(kp + i * 4);
                *(uint4*)(vd + i * 4) = *(const uint4*)(vp + i * 4);
            }
        }
        __syncthreads();

        float sc[8][4];
#pragma unroll
        for (int j = 0; j < 8; j++)
#pragma unroll
            for (int c = 0; c < 4; c++) sc[j][c] = 0.f;

#pragma unroll
        for (int ks = 0; ks < 10; ks++) {
#pragma unroll
            for (int j = 0; j < 8; j++) {
                uint32_t b[2];
                b[0] = Ks[(j * 8 + r) * KS_LD + ks * 8 + cq];
                b[1] = Ks[(j * 8 + r) * KS_LD + ks * 8 + cq + 4];
                mma_tf32(sc[j], qa[ks], b);
            }
        }

        float mx0 = -1e30f, mx1 = -1e30f;
#pragma unroll
        for (int j = 0; j < 8; j++) {
            mx0 = fmaxf(mx0, fmaxf(sc[j][0], sc[j][1]));
            mx1 = fmaxf(mx1, fmaxf(sc[j][2], sc[j][3]));
        }
        mx0 = fmaxf(mx0, __shfl_xor_sync(0xffffffffu, mx0, 1));
        mx0 = fmaxf(mx0, __shfl_xor_sync(0xffffffffu, mx0, 2));
        mx1 = fmaxf(mx1, __shfl_xor_sync(0xffffffffu, mx1, 1));
        mx1 = fmaxf(mx1, __shfl_xor_sync(0xffffffffu, mx1, 2));
        const float nm0 = fmaxf(m0, mx0);
        const float nm1 = fmaxf(m1, mx1);
        const float corr0 = __expf(m0 - nm0);
        const float corr1 = __expf(m1 - nm1);
        m0 = nm0; m1 = nm1;

        float sum0 = 0.f, sum1 = 0.f;
#pragma unroll
        for (int j = 0; j < 8; j++) {
            sc[j][0] = __expf(sc[j][0] - nm0);
            sc[j][1] = __expf(sc[j][1] - nm0);
            sc[j][2] = __expf(sc[j][2] - nm1);
            sc[j][3] = __expf(sc[j][3] - nm1);
            sum0 += sc[j][0] + sc[j][1];
            sum1 += sc[j][2] + sc[j][3];
        }
        sum0 += __shfl_xor_sync(0xffffffffu, sum0, 1);
        sum0 += __shfl_xor_sync(0xffffffffu, sum0, 2);
        sum1 += __shfl_xor_sync(0xffffffffu, sum1, 1);
        sum1 += __shfl_xor_sync(0xffffffffu, sum1, 2);
        l0 = l0 * corr0 + sum0;
        l1 = l1 * corr1 + sum1;

#pragma unroll
        for (int v = 0; v < 10; v++) {
            oacc[v][0] *= corr0; oacc[v][1] *= corr0;
            oacc[v][2] *= corr1; oacc[v][3] *= corr1;
        }

        const int srcA = r * 4 + (cq >> 1);
        const int srcB = srcA + 2;
        const bool odd = cq & 1;
#pragma unroll
        for (int s = 0; s < 8; s++) {
            float x0 = __shfl_sync(0xffffffffu, sc[s][0], srcA);
            float x1 = __shfl_sync(0xffffffffu, sc[s][1], srcA);
            float y0 = __shfl_sync(0xffffffffu, sc[s][2], srcA);
            float y1 = __shfl_sync(0xffffffffu, sc[s][3], srcA);
            float z0 = __shfl_sync(0xffffffffu, sc[s][0], srcB);
            float z1 = __shfl_sync(0xffffffffu, sc[s][1], srcB);
            float u0 = __shfl_sync(0xffffffffu, sc[s][2], srcB);
            float u1 = __shfl_sync(0xffffffffu, sc[s][3], srcB);
            uint32_t pa[4];
            pa[0] = f2tf32(odd ? x1 : x0);
            pa[1] = f2tf32(odd ? y1 : y0);
            pa[2] = f2tf32(odd ? z1 : z0);
            pa[3] = f2tf32(odd ? u1 : u0);
#pragma unroll
            for (int v = 0; v < 10; v++) {
                uint32_t b[2];
                b[0] = Vs[(s * 8 + cq) * VS_LD + v * 8 + r];
                b[1] = Vs[(s * 8 + cq + 4) * VS_LD + v * 8 + r];
                mma_tf32(oacc[v], pa, b);
            }
        }
    }

    // Epilogue (write tf32-rounded: proj GEMM consumes as tf32)
    const float inv0 = 1.f / l0;
    const float inv1 = 1.f / l1;
    float* O0 = g_attn + (size_t)(qrow + r) * DIM + hoff;
    float* O1 = g_attn + (size_t)(qrow + r + 8) * DIM + hoff;
#pragma unroll
    for (int v = 0; v < 10; v++) {
        float2 o;
        o.x = __uint_as_float(f2tf32(oacc[v][0] * inv0));
        o.y = __uint_as_float(f2tf32(oacc[v][1] * inv0));
        *(float2*)(O0 + v * 8 + 2 * cq) = o;
        o.x = __uint_as_float(f2tf32(oacc[v][2] * inv1));
        o.y = __uint_as_float(f2tf32(oacc[v][3] * inv1));
        *(float2*)(O1 + v * 8 + 2 * cq) = o;
    }
}

// ---------------------------------------------------------------------------
extern "C" void kernel_launch(void* const* d_in, const int* in_sizes, int n_in,
                              void* d_out, int out_size)
{
    const float* hs     = (const float*)d_in[0];
    const float* cosp   = (const float*)d_in[1];
    const float* sinp   = (const float*)d_in[2];
    const float* qkv_w  = (const float*)d_in[3];
    const float* qkv_b  = (const float*)d_in[4];
    const float* proj_w = (const float*)d_in[5];
    const float* proj_b = (const float*)d_in[6];
    float* out = (float*)d_out;

    float *qkv_ptr, *attn_ptr, *hs_ptr, *wq_ptr, *wp_ptr;
    cudaGetSymbolAddress((void**)&qkv_ptr, g_qkv);
    cudaGetSymbolAddress((void**)&attn_ptr, g_attn);
    cudaGetSymbolAddress((void**)&hs_ptr, g_hs);
    cudaGetSymbolAddress((void**)&wq_ptr, g_wq);
    cudaGetSymbolAddress((void**)&wp_ptr, g_wp);

    cudaFuncSetAttribute(gemm_tf32_pipe,
                         cudaFuncAttributeMaxDynamicSharedMemorySize, GEMM_SMEM);

    // 0) Pre-round GEMM inputs to tf32
    {
        int n4 = S_TOK * DIM / 4;
        round_tf32_kernel<<<(n4 + 255) / 256, 256>>>((const float4*)hs, (float4*)hs_ptr, n4);
        n4 = DIM3 * DIM / 4;
        round_tf32_kernel<<<(n4 + 255) / 256, 256>>>((const float4*)qkv_w, (float4*)wq_ptr, n4);
        n4 = DIM * DIM / 4;
        round_tf32_kernel<<<(n4 + 255) / 256, 256>>>((const float4*)proj_w, (float4*)wp_ptr, n4);
    }

    // 1) QKV GEMM + bias (pipelined tf32 mma), round outputs
    dim3 g1(DIM3 / 128, S_TOK / 128);
    gemm_tf32_pipe<<<g1, 256, GEMM_SMEM>>>(hs_ptr, wq_ptr, qkv_b, qkv_ptr, DIM3, 1);

    // 2) RoPE (folds softmax scale into Q, rounds outputs)
    int total = S_TOK * DIM;
    rope_kernel<<<(total + 255) / 256, 256>>>(cosp, sinp);

    // 3) Tensor-core flash attention
    dim3 g2(SEGLEN / 128, NH, NSEG);
    attn_mma<<<g2, 256>>>();

    // 4) Output projection + bias (exact fp32 output)
    dim3 g3(DIM / 128, S_TOK / 128);
    gemm_tf32_pipe<<<g3, 256, GEMM_SMEM>>>(attn_ptr, wp_ptr, proj_b, out, DIM, 0);
}

// round 9
// speedup vs baseline: 3.4908x; 1.0244x over previous
#include <cuda_runtime.h>
#include <cstdint>
#include <cstddef>

#define S_TOK 8192
#define DIM 1280
#define DIM3 3840
#define NH 16
#define DH 80
#define NSEG 8
#define SEGLEN 1024
#define GK 1280          // GEMM K (both GEMMs)
#define GNT (GK / 16)    // 80 k-tiles

// Scratch (device globals: allocation-free per harness rules)
__device__ float g_qkv[S_TOK * DIM3];   // qkv = hs @ qkv_w^T + b (tf32-rounded)
__device__ float g_q[S_TOK * DIM];      // roped Q * scale (tf32-rounded)
__device__ float g_k[S_TOK * DIM];      // roped K (tf32-rounded)
__device__ float g_attn[S_TOK * DIM];   // attention out (tf32-rounded)
__device__ float g_hs[S_TOK * DIM];     // tf32-rounded hidden_states
__device__ float g_wq[DIM3 * DIM];      // tf32-rounded qkv_w
__device__ float g_wp[DIM * DIM];      // tf32-rounded proj_w

// ---------------------------------------------------------------------------
// tf32 helpers (baseline PTX, no arch-specific features)
// ---------------------------------------------------------------------------
__device__ __forceinline__ uint32_t f2tf32(float x) {
    uint32_t r;
    asm("cvt.rna.tf32.f32 %0, %1;" : "=r"(r) : "f"(x));
    return r;
}

__device__ __forceinline__ void mma_tf32(float* c, const uint32_t* a, const uint32_t* b) {
    asm volatile(
        "mma.sync.aligned.m16n8k8.row.col.f32.tf32.tf32.f32 "
        "{%0,%1,%2,%3}, {%4,%5,%6,%7}, {%8,%9}, {%0,%1,%2,%3};"
        : "+f"(c[0]), "+f"(c[1]), "+f"(c[2]), "+f"(c[3])
        : "r"(a[0]), "r"(a[1]), "r"(a[2]), "r"(a[3]), "r"(b[0]), "r"(b[1]));
}

__device__ __forceinline__ void ldsm_x4(uint32_t* r, uint32_t addr) {
    asm volatile(
        "ldmatrix.sync.aligned.m8n8.x4.shared.b16 {%0,%1,%2,%3}, [%4];"
        : "=r"(r[0]), "=r"(r[1]), "=r"(r[2]), "=r"(r[3]) : "r"(addr));
}

__device__ __forceinline__ uint32_t smem_addr_u32(const void* p) {
    return (uint32_t)__cvta_generic_to_shared(p);
}

// ---------------------------------------------------------------------------
// Pre-round fp32 -> tf32-valued fp32 (vectorized)
// ---------------------------------------------------------------------------
__global__ void round_tf32_kernel(const float4* __restrict__ src,
                                  float4* __restrict__ dst, int n4)
{
    int i = blockIdx.x * blockDim.x + threadIdx.x;
    if (i >= n4) return;
    float4 v = src[i];
    float4 o;
    o.x = __uint_as_float(f2tf32(v.x));
    o.y = __uint_as_float(f2tf32(v.y));
    o.z = __uint_as_float(f2tf32(v.z));
    o.w = __uint_as_float(f2tf32(v.w));
    dst[i] = o;
}

// ---------------------------------------------------------------------------
// tf32 tensor-core GEMM (NT): C[M,N] = A[M,1280] @ B[N,1280]^T + bias[N]
// Inputs pre-rounded to tf32. BM=BN=128, BK=16, 256 threads (8 warps, 2Mx4N).
// 4-stage cp.async pipeline; fragments via ldmatrix.  (validated R8)
// ---------------------------------------------------------------------------
#define GLD 20
#define STAGES 4
#define STAGE_U32 (128 * GLD)
#define GEMM_SMEM (STAGES * 2 * STAGE_U32 * 4)   // 81920 B

__global__ __launch_bounds__(256, 2) void gemm_tf32_pipe(
    const float* __restrict__ A, const float* __restrict__ B,
    const float* __restrict__ bias, float* __restrict__ C,
    int N, int round_out)
{
    extern __shared__ uint32_t smp[];
    uint32_t* As = smp;
    uint32_t* Bs = smp + STAGES * STAGE_U32;

    const int tid = threadIdx.x;
    const int lane = tid & 31;
    const int wid = tid >> 5;
    const int wm = (wid & 1) * 64;
    const int wn = (wid >> 1) * 32;
    const int bm = blockIdx.y * 128;
    const int bn = blockIdx.x * 128;

    const int lrow = tid >> 1;
    const int lhalf = (tid & 1) * 8;
    const float* Ag = A + (size_t)(bm + lrow) * GK + lhalf;
    const float* Bg = B + (size_t)(bn + lrow) * GK + lhalf;

    const uint32_t As_base = smem_addr_u32(As);
    const uint32_t Bs_base = smem_addr_u32(Bs);
    const uint32_t stage_bytes = STAGE_U32 * 4;
    const uint32_t sA = As_base + (uint32_t)(lrow * GLD + lhalf) * 4;
    const uint32_t sB = Bs_base + (uint32_t)(lrow * GLD + lhalf) * 4;

    const int a_off = (wm + (lane & 15)) * GLD + ((lane >> 4) << 2);
    const int b_off = (wn + (lane & 7) + ((lane >> 4) << 3)) * GLD +
                      (((lane >> 3) & 1) << 2);

    float acc[4][4][4];
#pragma unroll
    for (int i = 0; i < 4; i++)
#pragma unroll
        for (int j = 0; j < 4; j++)
#pragma unroll
            for (int c = 0; c < 4; c++) acc[i][j][c] = 0.f;

#define ISSUE(ktv) do {                                                      \
    const int _st = (ktv) % STAGES;                                          \
    const float* _ap = Ag + (ktv) * 16;                                      \
    const float* _bp = Bg + (ktv) * 16;                                      \
    uint32_t _da = sA + _st * stage_bytes;                                   \
    uint32_t _db = sB + _st * stage_bytes;                                   \
    asm volatile(                                                            \
        "cp.async.cg.shared.global [%0], [%1], 16;\n\t"                      \
        "cp.async.cg.shared.global [%2], [%3], 16;\n\t"                      \
        "cp.async.cg.shared.global [%4], [%5], 16;\n\t"                      \
        "cp.async.cg.shared.global [%6], [%7], 16;\n\t"                      \
        "cp.async.commit_group;"                                             \
        :: "r"(_da), "l"(_ap), "r"(_da + 16), "l"(_ap + 4),                  \
           "r"(_db), "l"(_bp), "r"(_db + 16), "l"(_bp + 4) : "memory");      \
} while (0)

#pragma unroll
    for (int s = 0; s < STAGES - 1; s++) ISSUE(s);

    for (int kt = 0; kt < GNT; ++kt) {
        const int st = kt % STAGES;
        asm volatile("cp.async.wait_group %0;" :: "n"(STAGES - 2));
        __syncthreads();
        if (kt + STAGES - 1 < GNT) ISSUE(kt + STAGES - 1);

        const uint32_t a_base = As_base + st * stage_bytes + a_off * 4;
        const uint32_t b_base = Bs_base + st * stage_bytes + b_off * 4;
#pragma unroll
        for (int ks = 0; ks < 2; ++ks) {
            const uint32_t kcb = ks * 8 * 4;
            uint32_t af[4][4], bq[2][4];
#pragma unroll
            for (int i = 0; i < 4; i++)
                ldsm_x4(af[i], a_base + (uint32_t)(i * 16 * GLD * 4) + kcb);
#pragma unroll
            for (int jp = 0; jp < 2; jp++)
                ldsm_x4(bq[jp], b_base + (uint32_t)(jp * 16 * GLD * 4) + kcb);
#pragma unroll
            for (int i = 0; i < 4; i++)
#pragma unroll
                for (int j = 0; j < 4; j++)
                    mma_tf32(acc[i][j], af[i], &bq[j >> 1][(j & 1) * 2]);
        }
    }
#undef ISSUE

    const int r = lane >> 2;
    const int cq = lane & 3;
#pragma unroll
    for (int i = 0; i < 4; i++) {
        const int row0 = bm + wm + i * 16 + r;
#pragma unroll
        for (int j = 0; j < 4; j++) {
            const int col = bn + wn + j * 8 + cq * 2;
            const float b0 = bias[col], b1 = bias[col + 1];
            float2 v;
            v.x = acc[i][j][0] + b0;
            v.y = acc[i][j][1] + b1;
            if (round_out) {
                v.x = __uint_as_float(f2tf32(v.x));
                v.y = __uint_as_float(f2tf32(v.y));
            }
            *(float2*)(C + (size_t)row0 * N + col) = v;
            v.x = acc[i][j][2] + b0;
            v.y = acc[i][j][3] + b1;
            if (round_out) {
                v.x = __uint_as_float(f2tf32(v.x));
                v.y = __uint_as_float(f2tf32(v.y));
            }
            *(float2*)(C + (size_t)(row0 + 8) * N + col) = v;
        }
    }
}

// ---------------------------------------------------------------------------
// RoPE: q <- round((q*cos + rot(q)*sin) * scale), k <- round(k*cos + rot(k)*sin)
// ---------------------------------------------------------------------------
__global__ void rope_kernel(const float* __restrict__ cosp,
                            const float* __restrict__ sinp)
{
    int idx = blockIdx.x * blockDim.x + threadIdx.x;
    if (idx >= S_TOK * DIM) return;
    int s = idx / DIM;
    int c = idx - s * DIM;
    int d = c % DH;
    float cv = cosp[s * DH + d];
    float sv = sinp[s * DH + d];
    const float* row = g_qkv + (size_t)s * DIM3;
    float qv = row[c];
    float kv = row[DIM + c];
    float qr, kr;
    if (d < DH / 2) {
        qr = -row[c + DH / 2];
        kr = -row[DIM + c + DH / 2];
    } else {
        qr = row[c - DH / 2];
        kr = row[DIM + c - DH / 2];
    }
    const float scale = 0.11180339887498949f; // 1/sqrt(80)
    g_q[idx] = __uint_as_float(f2tf32(fmaf(qv, cv, qr * sv) * scale));
    g_k[idx] = __uint_as_float(f2tf32(fmaf(kv, cv, kr * sv)));
}

// ---------------------------------------------------------------------------
// Tensor-core flash attention (tf32 mma, fp32 accumulate).
// Double-buffered cp.async K/V staging; K fragments via ldmatrix.
// ---------------------------------------------------------------------------
#define KS_LD 84
#define VS_LD 88
#define KBUF_U32 (64 * KS_LD)
#define VBUF_U32 (64 * VS_LD)
#define ATT_SMEM ((2 * KBUF_U32 + 2 * VBUF_U32) * 4)   // 88064 B

__global__ __launch_bounds__(256, 1) void attn_mma()
{
    extern __shared__ uint32_t asmem[];
    uint32_t* Ksm = asmem;                    // [2][64][KS_LD]
    uint32_t* Vsm = asmem + 2 * KBUF_U32;     // [2][64][VS_LD]

    const int tid = threadIdx.x;
    const int lane = tid & 31;
    const int w = tid >> 5;
    const int r = lane >> 2;
    const int cq = lane & 3;

    const int qb = blockIdx.x;
    const int h = blockIdx.y;
    const int seg = blockIdx.z;
    const int q0 = seg * SEGLEN + qb * 128;
    const int qrow = q0 + w * 16;
    const int hoff = h * DH;

    const uint32_t Ks_base = smem_addr_u32(Ksm);
    const uint32_t Vs_base = smem_addr_u32(Vsm);

    // fill mapping: thread -> (token = tid>>2, 20 floats at (tid&3)*20)
    const int srow = tid >> 2;
    const int scol = (tid & 3) * 20;
    const uint32_t kfill = Ks_base + (uint32_t)(srow * KS_LD + scol) * 4;
    const uint32_t vfill = Vs_base + (uint32_t)(srow * VS_LD + scol) * 4;

#define AISSUE(kvtv, buf) do {                                               \
    const int _tok = seg * SEGLEN + (kvtv) * 64 + srow;                      \
    const float* _kp = g_k + (size_t)_tok * DIM + hoff + scol;               \
    const float* _vp = g_qkv + (size_t)_tok * DIM3 + 2 * DIM + hoff + scol;  \
    const uint32_t _kd = kfill + (buf) * (KBUF_U32 * 4);                     \
    const uint32_t _vd = vfill + (buf) * (VBUF_U32 * 4);                     \
    asm volatile(                                                            \
        "cp.async.cg.shared.global [%0], [%5], 16;\n\t"                      \
        "cp.async.cg.shared.global [%1], [%6], 16;\n\t"                      \
        "cp.async.cg.shared.global [%2], [%7], 16;\n\t"                      \
        "cp.async.cg.shared.global [%3], [%8], 16;\n\t"                      \
        "cp.async.cg.shared.global [%4], [%9], 16;\n\t"                      \
        :: "r"(_kd), "r"(_kd + 16), "r"(_kd + 32), "r"(_kd + 48),            \
           "r"(_kd + 64),                                                    \
           "l"(_kp), "l"(_kp + 4), "l"(_kp + 8), "l"(_kp + 12),              \
           "l"(_kp + 16) : "memory");                                        \
    asm volatile(                                                            \
        "cp.async.cg.shared.global [%0], [%5], 16;\n\t"                      \
        "cp.async.cg.shared.global [%1], [%6], 16;\n\t"                      \
        "cp.async.cg.shared.global [%2], [%7], 16;\n\t"                      \
        "cp.async.cg.shared.global [%3], [%8], 16;\n\t"                      \
        "cp.async.cg.shared.global [%4], [%9], 16;\n\t"                      \
        "cp.async.commit_group;"                                             \
        :: "r"(_vd), "r"(_vd + 16), "r"(_vd + 32), "r"(_vd + 48),            \
           "r"(_vd + 64),                                                    \
           "l"(_vp), "l"(_vp + 4), "l"(_vp + 8), "l"(_vp + 12),              \
           "l"(_vp + 16) : "memory");                                        \
} while (0)

    // Q fragments (pre-rounded, scale folded in by RoPE)
    uint32_t qa[10][4];
    {
        const float* Qb = g_q + (size_t)qrow * DIM + hoff;
#pragma unroll
        for (int ks = 0; ks < 10; ks++) {
            qa[ks][0] = __float_as_uint(Qb[(size_t)r * DIM + ks * 8 + cq]);
            qa[ks][1] = __float_as_uint(Qb[(size_t)(r + 8) * DIM + ks * 8 + cq]);
            qa[ks][2] = __float_as_uint(Qb[(size_t)r * DIM + ks * 8 + cq + 4]);
            qa[ks][3] = __float_as_uint(Qb[(size_t)(r + 8) * DIM + ks * 8 + cq + 4]);
        }
    }

    float m0 = -1e30f, m1 = -1e30f, l0 = 0.f, l1 = 0.f;
    float oacc[10][4];
#pragma unroll
    for (int v = 0; v < 10; v++)
#pragma unroll
        for (int c = 0; c < 4; c++) oacc[v][c] = 0.f;

    // ldmatrix K offset (uint32 units within a K buffer): rows=token, cols=k
    const int kb_off = ((lane & 7) + ((lane >> 4) << 3)) * KS_LD +
                       (((lane >> 3) & 1) << 2);

    AISSUE(0, 0);

    for (int kvt = 0; kvt < 16; kvt++) {
        const int buf = kvt & 1;
        asm volatile("cp.async.wait_group 0;" ::: "memory");
        __syncthreads();
        if (kvt + 1 < 16) AISSUE(kvt + 1, buf ^ 1);

        const uint32_t kbase = Ks_base + buf * (KBUF_U32 * 4) + kb_off * 4;
        const uint32_t* Vb = Vsm + buf * VBUF_U32;

        // S = Q K^T : ldmatrix x4 covers token-pairs (2j) x both k-halves
        float sc[8][4];
#pragma unroll
        for (int j = 0; j < 8; j++)
#pragma unroll
            for (int c = 0; c < 4; c++) sc[j][c] = 0.f;

#pragma unroll
        for (int ks = 0; ks < 10; ks++) {
            uint32_t bq[4][4];
#pragma unroll
            for (int jp = 0; jp < 4; jp++)
                ldsm_x4(bq[jp], kbase + (uint32_t)(jp * 16 * KS_LD * 4) +
                                (uint32_t)(ks * 8 * 4));
#pragma unroll
            for (int jp = 0; jp < 4; jp++) {
                mma_tf32(sc[jp * 2], qa[ks], &bq[jp][0]);
                mma_tf32(sc[jp * 2 + 1], qa[ks], &bq[jp][2]);
            }
        }

        // Online softmax
        float mx0 = -1e30f, mx1 = -1e30f;
#pragma unroll
        for (int j = 0; j < 8; j++) {
            mx0 = fmaxf(mx0, fmaxf(sc[j][0], sc[j][1]));
            mx1 = fmaxf(mx1, fmaxf(sc[j][2], sc[j][3]));
        }
        mx0 = fmaxf(mx0, __shfl_xor_sync(0xffffffffu, mx0, 1));
        mx0 = fmaxf(mx0, __shfl_xor_sync(0xffffffffu, mx0, 2));
        mx1 = fmaxf(mx1, __shfl_xor_sync(0xffffffffu, mx1, 1));
        mx1 = fmaxf(mx1, __shfl_xor_sync(0xffffffffu, mx1, 2));
        const float nm0 = fmaxf(m0, mx0);
        const float nm1 = fmaxf(m1, mx1);
        const float corr0 = __expf(m0 - nm0);
        const float corr1 = __expf(m1 - nm1);
        m0 = nm0; m1 = nm1;

        float sum0 = 0.f, sum1 = 0.f;
#pragma unroll
        for (int j = 0; j < 8; j++) {
            sc[j][0] = __expf(sc[j][0] - nm0);
            sc[j][1] = __expf(sc[j][1] - nm0);
            sc[j][2] = __expf(sc[j][2] - nm1);
            sc[j][3] = __expf(sc[j][3] - nm1);
            sum0 += sc[j][0] + sc[j][1];
            sum1 += sc[j][2] + sc[j][3];
        }
        sum0 += __shfl_xor_sync(0xffffffffu, sum0, 1);
        sum0 += __shfl_xor_sync(0xffffffffu, sum0, 2);
        sum1 += __shfl_xor_sync(0xffffffffu, sum1, 1);
        sum1 += __shfl_xor_sync(0xffffffffu, sum1, 2);
        l0 = l0 * corr0 + sum0;
        l1 = l1 * corr1 + sum1;

#pragma unroll
        for (int v = 0; v < 10; v++) {
            oacc[v][0] *= corr0; oacc[v][1] *= corr0;
            oacc[v][2] *= corr1; oacc[v][3] *= corr1;
        }

        // P C-frag -> A-frag via shuffles, then O += P V
        const int srcA = r * 4 + (cq >> 1);
        const int srcB = srcA + 2;
        const bool odd = cq & 1;
#pragma unroll
        for (int s = 0; s < 8; s++) {
            float x0 = __shfl_sync(0xffffffffu, sc[s][0], srcA);
            float x1 = __shfl_sync(0xffffffffu, sc[s][1], srcA);
            float y0 = __shfl_sync(0xffffffffu, sc[s][2], srcA);
            float y1 = __shfl_sync(0xffffffffu, sc[s][3], srcA);
            float z0 = __shfl_sync(0xffffffffu, sc[s][0], srcB);
            float z1 = __shfl_sync(0xffffffffu, sc[s][1], srcB);
            float u0 = __shfl_sync(0xffffffffu, sc[s][2], srcB);
            float u1 = __shfl_sync(0xffffffffu, sc[s][3], srcB);
            uint32_t pa[4];
            pa[0] = f2tf32(odd ? x1 : x0);
            pa[1] = f2tf32(odd ? y1 : y0);
            pa[2] = f2tf32(odd ? z1 : z0);
            pa[3] = f2tf32(odd ? u1 : u0);
#pragma unroll
            for (int v = 0; v < 10; v++) {
                uint32_t b[2];
                b[0] = Vb[(s * 8 + cq) * VS_LD + v * 8 + r];
                b[1] = Vb[(s * 8 + cq + 4) * VS_LD + v * 8 + r];
                mma_tf32(oacc[v], pa, b);
            }
        }
    }
#undef AISSUE

    // Epilogue (tf32-rounded: proj GEMM consumes as tf32)
    const float inv0 = 1.f / l0;
    const float inv1 = 1.f / l1;
    float* O0 = g_attn + (size_t)(qrow + r) * DIM + hoff;
    float* O1 = g_attn + (size_t)(qrow + r + 8) * DIM + hoff;
#pragma unroll
    for (int v = 0; v < 10; v++) {
        float2 o;
        o.x = __uint_as_float(f2tf32(oacc[v][0] * inv0));
        o.y = __uint_as_float(f2tf32(oacc[v][1] * inv0));
        *(float2*)(O0 + v * 8 + 2 * cq) = o;
        o.x = __uint_as_float(f2tf32(oacc[v][2] * inv1));
        o.y = __uint_as_float(f2tf32(oacc[v][3] * inv1));
        *(float2*)(O1 + v * 8 + 2 * cq) = o;
    }
}

// ---------------------------------------------------------------------------
extern "C" void kernel_launch(void* const* d_in, const int* in_sizes, int n_in,
                              void* d_out, int out_size)
{
    const float* hs     = (const float*)d_in[0];
    const float* cosp   = (const float*)d_in[1];
    const float* sinp   = (const float*)d_in[2];
    const float* qkv_w  = (const float*)d_in[3];
    const float* qkv_b  = (const float*)d_in[4];
    const float* proj_w = (const float*)d_in[5];
    const float* proj_b = (const float*)d_in[6];
    float* out = (float*)d_out;

    float *qkv_ptr, *attn_ptr, *hs_ptr, *wq_ptr, *wp_ptr;
    cudaGetSymbolAddress((void**)&qkv_ptr, g_qkv);
    cudaGetSymbolAddress((void**)&attn_ptr, g_attn);
    cudaGetSymbolAddress((void**)&hs_ptr, g_hs);
    cudaGetSymbolAddress((void**)&wq_ptr, g_wq);
    cudaGetSymbolAddress((void**)&wp_ptr, g_wp);

    cudaFuncSetAttribute(gemm_tf32_pipe,
                         cudaFuncAttributeMaxDynamicSharedMemorySize, GEMM_SMEM);
    cudaFuncSetAttribute(attn_mma,
                         cudaFuncAttributeMaxDynamicSharedMemorySize, ATT_SMEM);

    // 0) Pre-round GEMM inputs to tf32
    {
        int n4 = S_TOK * DIM / 4;
        round_tf32_kernel<<<(n4 + 255) / 256, 256>>>((const float4*)hs, (float4*)hs_ptr, n4);
        n4 = DIM3 * DIM / 4;
        round_tf32_kernel<<<(n4 + 255) / 256, 256>>>((const float4*)qkv_w, (float4*)wq_ptr, n4);
        n4 = DIM * DIM / 4;
        round_tf32_kernel<<<(n4 + 255) / 256, 256>>>((const float4*)proj_w, (float4*)wp_ptr, n4);
    }

    // 1) QKV GEMM + bias (pipelined tf32 mma), round outputs
    dim3 g1(DIM3 / 128, S_TOK / 128);
    gemm_tf32_pipe<<<g1, 256, GEMM_SMEM>>>(hs_ptr, wq_ptr, qkv_b, qkv_ptr, DIM3, 1);

    // 2) RoPE (folds softmax scale into Q, rounds outputs)
    int total = S_TOK * DIM;
    rope_kernel<<<(total + 255) / 256, 256>>>(cosp, sinp);

    // 3) Tensor-core flash attention (pipelined)
    dim3 g2(SEGLEN / 128, NH, NSEG);
    attn_mma<<<g2, 256, ATT_SMEM>>>();

    // 4) Output projection + bias (exact fp32 output)
    dim3 g3(DIM / 128, S_TOK / 128);
    gemm_tf32_pipe<<<g3, 256, GEMM_SMEM>>>(attn_ptr, wp_ptr, proj_b, out, DIM, 0);
}

// round 10
// speedup vs baseline: 6.8203x; 1.9538x over previous
#include <cuda_runtime.h>
#include <cuda_fp16.h>
#include <cstdint>
#include <cstddef>

#define S_TOK 8192
#define DIM 1280
#define DIM3 3840
#define NH 16
#define DH 80
#define NSEG 8
#define SEGLEN 1024
#define GK 1280           // GEMM K (halves)
#define GBK 32            // GEMM k per tile (halves)
#define GNT (GK / GBK)    // 40 k-tiles

// Scratch (device globals: allocation-free per harness rules)
__device__ __half g_qkv16[S_TOK * DIM3];  // qkv result (fp16)
__device__ __half g_q16[S_TOK * DIM];     // roped Q * scale (fp16)
__device__ __half g_k16[S_TOK * DIM];     // roped K (fp16)
__device__ __half g_attn16[S_TOK * DIM];  // attention out (fp16)
__device__ __half g_hs16[S_TOK * DIM];    // fp16 hidden_states
__device__ __half g_wq16[DIM3 * DIM];     // fp16 qkv_w
__device__ __half g_wp16[DIM * DIM];      // fp16 proj_w

// ---------------------------------------------------------------------------
// helpers (baseline PTX, no arch-specific features)
// ---------------------------------------------------------------------------
__device__ __forceinline__ void mma_f16(float* c, const uint32_t* a, const uint32_t* b) {
    asm volatile(
        "mma.sync.aligned.m16n8k16.row.col.f32.f16.f16.f32 "
        "{%0,%1,%2,%3}, {%4,%5,%6,%7}, {%8,%9}, {%0,%1,%2,%3};"
        : "+f"(c[0]), "+f"(c[1]), "+f"(c[2]), "+f"(c[3])
        : "r"(a[0]), "r"(a[1]), "r"(a[2]), "r"(a[3]), "r"(b[0]), "r"(b[1]));
}

__device__ __forceinline__ void ldsm_x4(uint32_t* r, uint32_t addr) {
    asm volatile(
        "ldmatrix.sync.aligned.m8n8.x4.shared.b16 {%0,%1,%2,%3}, [%4];"
        : "=r"(r[0]), "=r"(r[1]), "=r"(r[2]), "=r"(r[3]) : "r"(addr));
}

__device__ __forceinline__ void ldsm_x4_t(uint32_t* r, uint32_t addr) {
    asm volatile(
        "ldmatrix.sync.aligned.m8n8.x4.trans.shared.b16 {%0,%1,%2,%3}, [%4];"
        : "=r"(r[0]), "=r"(r[1]), "=r"(r[2]), "=r"(r[3]) : "r"(addr));
}

__device__ __forceinline__ uint32_t smem_addr_u32(const void* p) {
    return (uint32_t)__cvta_generic_to_shared(p);
}

__device__ __forceinline__ uint32_t pack_h2(float a, float b) {
    __half2 h = __floats2half2_rn(a, b);
    return *(uint32_t*)&h;
}

// ---------------------------------------------------------------------------
// fp32 -> fp16 convert (vectorized)
// ---------------------------------------------------------------------------
__global__ void to_f16_kernel(const float4* __restrict__ src,
                              __half* __restrict__ dst, int n4)
{
    int i = blockIdx.x * blockDim.x + threadIdx.x;
    if (i >= n4) return;
    float4 v = src[i];
    uint2 o;
    o.x = pack_h2(v.x, v.y);
    o.y = pack_h2(v.z, v.w);
    *(uint2*)(dst + (size_t)i * 4) = o;
}

// ---------------------------------------------------------------------------
// fp16 tensor-core GEMM (NT): C[M,N] = A[M,1280] @ B[N,1280]^T + bias[N]
// BM=BN=128, BK=32 halves, 256 threads (8 warps, 2Mx4N, warp tile 64x32).
// 4-stage cp.async pipeline; all fragments via ldmatrix.
// ---------------------------------------------------------------------------
#define GLDH 40                            // smem row stride in halves
#define STAGES 4
#define STAGE_BYTES (128 * GLDH * 2)       // 10240
#define GEMM_SMEM (STAGES * 2 * STAGE_BYTES)  // 81920

__global__ __launch_bounds__(256, 2) void gemm_f16_pipe(
    const __half* __restrict__ A, const __half* __restrict__ B,
    const float* __restrict__ bias, void* __restrict__ Cout,
    int N, int half_out)
{
    extern __shared__ __half smp[];
    __half* As = smp;                                 // [STAGES][128][GLDH]
    __half* Bs = smp + STAGES * 128 * GLDH;

    const int tid = threadIdx.x;
    const int lane = tid & 31;
    const int wid = tid >> 5;
    const int wm = (wid & 1) * 64;
    const int wn = (wid >> 1) * 32;
    const int bm = blockIdx.y * 128;
    const int bn = blockIdx.x * 128;

    const int lrow = tid >> 1;            // 0..127
    const int lhh = (tid & 1) * 16;       // halves 0 or 16
    const __half* Ag = A + (size_t)(bm + lrow) * GK + lhh;
    const __half* Bg = B + (size_t)(bn + lrow) * GK + lhh;

    const uint32_t As_base = smem_addr_u32(As);
    const uint32_t Bs_base = smem_addr_u32(Bs);
    const uint32_t sA = As_base + (uint32_t)(lrow * GLDH + lhh) * 2;
    const uint32_t sB = Bs_base + (uint32_t)(lrow * GLDH + lhh) * 2;

    // ldmatrix lane offsets (bytes within a stage)
    const uint32_t a_off = ((uint32_t)(wm + (lane & 15)) * GLDH +
                            ((lane >> 4) << 3)) * 2;
    const uint32_t b_off = ((uint32_t)(wn + (lane & 7) + ((lane >> 4) << 3)) * GLDH +
                            (((lane >> 3) & 1) << 3)) * 2;

    float acc[4][4][4];
#pragma unroll
    for (int i = 0; i < 4; i++)
#pragma unroll
        for (int j = 0; j < 4; j++)
#pragma unroll
            for (int c = 0; c < 4; c++) acc[i][j][c] = 0.f;

#define ISSUE(ktv) do {                                                      \
    const int _st = (ktv) % STAGES;                                          \
    const __half* _ap = Ag + (ktv) * GBK;                                    \
    const __half* _bp = Bg + (ktv) * GBK;                                    \
    uint32_t _da = sA + _st * STAGE_BYTES;                                   \
    uint32_t _db = sB + _st * STAGE_BYTES;                                   \
    asm volatile(                                                            \
        "cp.async.cg.shared.global [%0], [%1], 16;\n\t"                      \
        "cp.async.cg.shared.global [%2], [%3], 16;\n\t"                      \
        "cp.async.cg.shared.global [%4], [%5], 16;\n\t"                      \
        "cp.async.cg.shared.global [%6], [%7], 16;\n\t"                      \
        "cp.async.commit_group;"                                             \
        :: "r"(_da), "l"(_ap), "r"(_da + 16), "l"(_ap + 8),                  \
           "r"(_db), "l"(_bp), "r"(_db + 16), "l"(_bp + 8) : "memory");      \
} while (0)

#pragma unroll
    for (int s = 0; s < STAGES - 1; s++) ISSUE(s);

    for (int kt = 0; kt < GNT; ++kt) {
        const int st = kt % STAGES;
        asm volatile("cp.async.wait_group %0;" :: "n"(STAGES - 2));
        __syncthreads();
        if (kt + STAGES - 1 < GNT) ISSUE(kt + STAGES - 1);

        const uint32_t a_base = As_base + st * STAGE_BYTES + a_off;
        const uint32_t b_base = Bs_base + st * STAGE_BYTES + b_off;
#pragma unroll
        for (int ks = 0; ks < 2; ++ks) {
            const uint32_t kcb = ks * 16 * 2;   // 16 halves per k-step
            uint32_t af[4][4], bq[2][4];
#pragma unroll
            for (int i = 0; i < 4; i++)
                ldsm_x4(af[i], a_base + (uint32_t)(i * 16 * GLDH * 2) + kcb);
#pragma unroll
            for (int jp = 0; jp < 2; jp++)
                ldsm_x4(bq[jp], b_base + (uint32_t)(jp * 16 * GLDH * 2) + kcb);
#pragma unroll
            for (int i = 0; i < 4; i++)
#pragma unroll
                for (int j = 0; j < 4; j++)
                    mma_f16(acc[i][j], af[i], &bq[j >> 1][(j & 1) * 2]);
        }
    }
#undef ISSUE

    const int r = lane >> 2;
    const int cq = lane & 3;
#pragma unroll
    for (int i = 0; i < 4; i++) {
        const int row0 = bm + wm + i * 16 + r;
#pragma unroll
        for (int j = 0; j < 4; j++) {
            const int col = bn + wn + j * 8 + cq * 2;
            const float b0 = bias[col], b1 = bias[col + 1];
            if (half_out) {
                __half* C16 = (__half*)Cout;
                *(uint32_t*)(C16 + (size_t)row0 * N + col) =
                    pack_h2(acc[i][j][0] + b0, acc[i][j][1] + b1);
                *(uint32_t*)(C16 + (size_t)(row0 + 8) * N + col) =
                    pack_h2(acc[i][j][2] + b0, acc[i][j][3] + b1);
            } else {
                float* C32 = (float*)Cout;
                float2 v;
                v.x = acc[i][j][0] + b0; v.y = acc[i][j][1] + b1;
                *(float2*)(C32 + (size_t)row0 * N + col) = v;
                v.x = acc[i][j][2] + b0; v.y = acc[i][j][3] + b1;
                *(float2*)(C32 + (size_t)(row0 + 8) * N + col) = v;
            }
        }
    }
}

// ---------------------------------------------------------------------------
// RoPE on fp16 qkv: q <- (q*cos + rot(q)*sin)*scale, k <- k*cos + rot(k)*sin
// ---------------------------------------------------------------------------
__global__ void rope16_kernel(const float* __restrict__ cosp,
                              const float* __restrict__ sinp)
{
    int idx = blockIdx.x * blockDim.x + threadIdx.x;
    if (idx >= S_TOK * DIM) return;
    int s = idx / DIM;
    int c = idx - s * DIM;
    int d = c % DH;
    float cv = cosp[s * DH + d];
    float sv = sinp[s * DH + d];
    const __half* row = g_qkv16 + (size_t)s * DIM3;
    float qv = __half2float(row[c]);
    float kv = __half2float(row[DIM + c]);
    float qr, kr;
    if (d < DH / 2) {
        qr = -__half2float(row[c + DH / 2]);
        kr = -__half2float(row[DIM + c + DH / 2]);
    } else {
        qr = __half2float(row[c - DH / 2]);
        kr = __half2float(row[DIM + c - DH / 2]);
    }
    const float scale = 0.11180339887498949f; // 1/sqrt(80)
    g_q16[idx] = __float2half_rn(fmaf(qv, cv, qr * sv) * scale);
    g_k16[idx] = __float2half_rn(fmaf(kv, cv, kr * sv));
}

// ---------------------------------------------------------------------------
// fp16 tensor-core flash attention. Block = 128 Q rows x (seg, head);
// 8 warps x 16 rows. Double-buffered cp.async K/V; K via ldmatrix,
// V via ldmatrix.trans; P packs locally into A-frags (no shuffles).
// ---------------------------------------------------------------------------
#define KVLD 88                            // K/V smem row stride (halves)
#define KVBUF_BYTES (64 * KVLD * 2)        // 11264
#define ATT_SMEM (4 * KVBUF_BYTES)         // 45056

__global__ __launch_bounds__(256, 1) void attn_f16()
{
    extern __shared__ __half asmem[];
    const uint32_t Ks_base = smem_addr_u32(asmem);
    const uint32_t Vs_base = Ks_base + 2 * KVBUF_BYTES;

    const int tid = threadIdx.x;
    const int lane = tid & 31;
    const int w = tid >> 5;
    const int r = lane >> 2;
    const int cq = lane & 3;

    const int qb = blockIdx.x;
    const int h = blockIdx.y;
    const int seg = blockIdx.z;
    const int qrow = seg * SEGLEN + qb * 128 + w * 16;
    const int hoff = h * DH;

#define AISSUE(kvtv, buf) do {                                               \
    const int _tb = seg * SEGLEN + (kvtv) * 64;                              \
    for (int _c = tid; _c < 640; _c += 256) {                                \
        int _row = _c / 10, _c16 = _c - _row * 10;                           \
        uint32_t _kd = Ks_base + (buf) * KVBUF_BYTES + _row * (KVLD * 2) + _c16 * 16; \
        uint32_t _vd = Vs_base + (buf) * KVBUF_BYTES + _row * (KVLD * 2) + _c16 * 16; \
        const __half* _kp = g_k16 + (size_t)(_tb + _row) * DIM + hoff + _c16 * 8; \
        const __half* _vp = g_qkv16 + (size_t)(_tb + _row) * DIM3 + 2 * DIM + hoff + _c16 * 8; \
        asm volatile(                                                        \
            "cp.async.cg.shared.global [%0], [%1], 16;\n\t"                  \
            "cp.async.cg.shared.global [%2], [%3], 16;\n\t"                  \
            :: "r"(_kd), "l"(_kp), "r"(_vd), "l"(_vp) : "memory");           \
    }                                                                        \
    asm volatile("cp.async.commit_group;" ::: "memory");                     \
} while (0)

    // Q fragments: 5 k-steps of 16 halves
    uint32_t qa[5][4];
    {
        const __half* Qb = g_q16 + (size_t)qrow * DIM + hoff;
#pragma unroll
        for (int ks = 0; ks < 5; ks++) {
            qa[ks][0] = *(const uint32_t*)(Qb + (size_t)r * DIM + ks * 16 + 2 * cq);
            qa[ks][1] = *(const uint32_t*)(Qb + (size_t)(r + 8) * DIM + ks * 16 + 2 * cq);
            qa[ks][2] = *(const uint32_t*)(Qb + (size_t)r * DIM + ks * 16 + 8 + 2 * cq);
            qa[ks][3] = *(const uint32_t*)(Qb + (size_t)(r + 8) * DIM + ks * 16 + 8 + 2 * cq);
        }
    }

    float m0 = -1e30f, m1 = -1e30f, l0 = 0.f, l1 = 0.f;
    float oacc[10][4];
#pragma unroll
    for (int v = 0; v < 10; v++)
#pragma unroll
        for (int c = 0; c < 4; c++) oacc[v][c] = 0.f;

    // ldmatrix lane offsets (bytes within a buffer)
    const uint32_t kb_off = ((uint32_t)((lane & 7) + ((lane >> 4) << 3)) * KVLD +
                            (((lane >> 3) & 1) << 3)) * 2;
    const uint32_t vb_off = ((uint32_t)((lane & 7) + (((lane >> 3) & 1) << 3)) * KVLD +
                            (((lane >> 4) & 1) << 3)) * 2;

    AISSUE(0, 0);

    for (int kvt = 0; kvt < 16; kvt++) {
        const int buf = kvt & 1;
        asm volatile("cp.async.wait_group 0;" ::: "memory");
        __syncthreads();
        if (kvt + 1 < 16) AISSUE(kvt + 1, buf ^ 1);

        const uint32_t kbase = Ks_base + buf * KVBUF_BYTES + kb_off;
        const uint32_t vbase = Vs_base + buf * KVBUF_BYTES + vb_off;

        // S = Q K^T
        float sc[8][4];
#pragma unroll
        for (int j = 0; j < 8; j++)
#pragma unroll
            for (int c = 0; c < 4; c++) sc[j][c] = 0.f;

#pragma unroll
        for (int ks = 0; ks < 5; ks++) {
#pragma unroll
            for (int jp = 0; jp < 4; jp++) {
                uint32_t bq[4];
                ldsm_x4(bq, kbase + (uint32_t)(jp * 16 * KVLD * 2) +
                            (uint32_t)(ks * 32));
                mma_f16(sc[jp * 2], qa[ks], &bq[0]);
                mma_f16(sc[jp * 2 + 1], qa[ks], &bq[2]);
            }
        }

        // Online softmax (C-frag layout: rows r / r+8)
        float mx0 = -1e30f, mx1 = -1e30f;
#pragma unroll
        for (int j = 0; j < 8; j++) {
            mx0 = fmaxf(mx0, fmaxf(sc[j][0], sc[j][1]));
            mx1 = fmaxf(mx1, fmaxf(sc[j][2], sc[j][3]));
        }
        mx0 = fmaxf(mx0, __shfl_xor_sync(0xffffffffu, mx0, 1));
        mx0 = fmaxf(mx0, __shfl_xor_sync(0xffffffffu, mx0, 2));
        mx1 = fmaxf(mx1, __shfl_xor_sync(0xffffffffu, mx1, 1));
        mx1 = fmaxf(mx1, __shfl_xor_sync(0xffffffffu, mx1, 2));
        const float nm0 = fmaxf(m0, mx0);
        const float nm1 = fmaxf(m1, mx1);
        const float corr0 = __expf(m0 - nm0);
        const float corr1 = __expf(m1 - nm1);
        m0 = nm0; m1 = nm1;

        float sum0 = 0.f, sum1 = 0.f;
#pragma unroll
        for (int j = 0; j < 8; j++) {
            sc[j][0] = __expf(sc[j][0] - nm0);
            sc[j][1] = __expf(sc[j][1] - nm0);
            sc[j][2] = __expf(sc[j][2] - nm1);
            sc[j][3] = __expf(sc[j][3] - nm1);
            sum0 += sc[j][0] + sc[j][1];
            sum1 += sc[j][2] + sc[j][3];
        }
        sum0 += __shfl_xor_sync(0xffffffffu, sum0, 1);
        sum0 += __shfl_xor_sync(0xffffffffu, sum0, 2);
        sum1 += __shfl_xor_sync(0xffffffffu, sum1, 1);
        sum1 += __shfl_xor_sync(0xffffffffu, sum1, 2);
        l0 = l0 * corr0 + sum0;
        l1 = l1 * corr1 + sum1;

#pragma unroll
        for (int v = 0; v < 10; v++) {
            oacc[v][0] *= corr0; oacc[v][1] *= corr0;
            oacc[v][2] *= corr1; oacc[v][3] *= corr1;
        }

        // O += P V : P packs locally (C-frag -> fp16 A-frag is lane-local)
#pragma unroll
        for (int t = 0; t < 4; t++) {
            uint32_t pa[4];
            pa[0] = pack_h2(sc[2 * t][0], sc[2 * t][1]);
            pa[1] = pack_h2(sc[2 * t][2], sc[2 * t][3]);
            pa[2] = pack_h2(sc[2 * t + 1][0], sc[2 * t + 1][1]);
            pa[3] = pack_h2(sc[2 * t + 1][2], sc[2 * t + 1][3]);
#pragma unroll
            for (int vp = 0; vp < 5; vp++) {
                uint32_t bv[4];
                ldsm_x4_t(bv, vbase + (uint32_t)(t * 16 * KVLD * 2) +
                              (uint32_t)(vp * 32));
                mma_f16(oacc[2 * vp], pa, &bv[0]);
                mma_f16(oacc[2 * vp + 1], pa, &bv[2]);
            }
        }
    }
#undef AISSUE

    // Epilogue: fp16 out (proj GEMM input)
    const float inv0 = 1.f / l0;
    const float inv1 = 1.f / l1;
    __half* O0 = g_attn16 + (size_t)(qrow + r) * DIM + hoff;
    __half* O1 = g_attn16 + (size_t)(qrow + r + 8) * DIM + hoff;
#pragma unroll
    for (int v = 0; v < 10; v++) {
        *(uint32_t*)(O0 + v * 8 + 2 * cq) =
            pack_h2(oacc[v][0] * inv0, oacc[v][1] * inv0);
        *(uint32_t*)(O1 + v * 8 + 2 * cq) =
            pack_h2(oacc[v][2] * inv1, oacc[v][3] * inv1);
    }
}

// ---------------------------------------------------------------------------
extern "C" void kernel_launch(void* const* d_in, const int* in_sizes, int n_in,
                              void* d_out, int out_size)
{
    const float* hs     = (const float*)d_in[0];
    const float* cosp   = (const float*)d_in[1];
    const float* sinp   = (const float*)d_in[2];
    const float* qkv_w  = (const float*)d_in[3];
    const float* qkv_b  = (const float*)d_in[4];
    const float* proj_w = (const float*)d_in[5];
    const float* proj_b = (const float*)d_in[6];
    float* out = (float*)d_out;

    __half *qkv_p, *attn_p, *hs_p, *wq_p, *wp_p;
    cudaGetSymbolAddress((void**)&qkv_p, g_qkv16);
    cudaGetSymbolAddress((void**)&attn_p, g_attn16);
    cudaGetSymbolAddress((void**)&hs_p, g_hs16);
    cudaGetSymbolAddress((void**)&wq_p, g_wq16);
    cudaGetSymbolAddress((void**)&wp_p, g_wp16);

    cudaFuncSetAttribute(gemm_f16_pipe,
                         cudaFuncAttributeMaxDynamicSharedMemorySize, GEMM_SMEM);
    cudaFuncSetAttribute(attn_f16,
                         cudaFuncAttributeMaxDynamicSharedMemorySize, ATT_SMEM);

    // 0) Convert GEMM inputs to fp16
    {
        int n4 = S_TOK * DIM / 4;
        to_f16_kernel<<<(n4 + 255) / 256, 256>>>((const float4*)hs, hs_p, n4);
        n4 = DIM3 * DIM / 4;
        to_f16_kernel<<<(n4 + 255) / 256, 256>>>((const float4*)qkv_w, wq_p, n4);
        n4 = DIM * DIM / 4;
        to_f16_kernel<<<(n4 + 255) / 256, 256>>>((const float4*)proj_w, wp_p, n4);
    }

    // 1) QKV GEMM + bias (fp16 tensor cores), fp16 output
    dim3 g1(DIM3 / 128, S_TOK / 128);
    gemm_f16_pipe<<<g1, 256, GEMM_SMEM>>>(hs_p, wq_p, qkv_b, qkv_p, DIM3, 1);

    // 2) RoPE (folds softmax scale into Q)
    int total = S_TOK * DIM;
    rope16_kernel<<<(total + 255) / 256, 256>>>(cosp, sinp);

    // 3) fp16 tensor-core flash attention
    dim3 g2(SEGLEN / 128, NH, NSEG);
    attn_f16<<<g2, 256, ATT_SMEM>>>();

    // 4) Output projection + bias (fp32 output)
    dim3 g3(DIM / 128, S_TOK / 128);
    gemm_f16_pipe<<<g3, 256, GEMM_SMEM>>>(attn_p, wp_p, proj_b, out, DIM, 0);
}

// round 11
// speedup vs baseline: 7.1542x; 1.0489x over previous
#include <cuda_runtime.h>
#include <cuda_fp16.h>
#include <cstdint>
#include <cstddef>

#define S_TOK 8192
#define DIM 1280
#define DIM3 3840
#define NH 16
#define DH 80
#define NSEG 8
#define SEGLEN 1024
#define GK 1280           // GEMM K (halves)
#define GBK 32            // GEMM k per tile (halves)
#define GNT (GK / GBK)    // 40 k-tiles

// Scratch (device globals: allocation-free per harness rules)
__device__ __half g_qkv16[S_TOK * DIM3];  // qkv result (fp16)
__device__ __half g_q16[S_TOK * DIM];     // roped Q * scale (fp16)
__device__ __half g_k16[S_TOK * DIM];     // roped K (fp16)
__device__ __half g_attn16[S_TOK * DIM];  // attention out (fp16)
__device__ __half g_hs16[S_TOK * DIM];    // fp16 hidden_states
__device__ __half g_wq16[DIM3 * DIM];     // fp16 qkv_w
__device__ __half g_wp16[DIM * DIM];      // fp16 proj_w

// ---------------------------------------------------------------------------
// helpers (baseline PTX, no arch-specific features)
// ---------------------------------------------------------------------------
__device__ __forceinline__ void mma_f16(float* c, const uint32_t* a, const uint32_t* b) {
    asm volatile(
        "mma.sync.aligned.m16n8k16.row.col.f32.f16.f16.f32 "
        "{%0,%1,%2,%3}, {%4,%5,%6,%7}, {%8,%9}, {%0,%1,%2,%3};"
        : "+f"(c[0]), "+f"(c[1]), "+f"(c[2]), "+f"(c[3])
        : "r"(a[0]), "r"(a[1]), "r"(a[2]), "r"(a[3]), "r"(b[0]), "r"(b[1]));
}

__device__ __forceinline__ void ldsm_x4(uint32_t* r, uint32_t addr) {
    asm volatile(
        "ldmatrix.sync.aligned.m8n8.x4.shared.b16 {%0,%1,%2,%3}, [%4];"
        : "=r"(r[0]), "=r"(r[1]), "=r"(r[2]), "=r"(r[3]) : "r"(addr));
}

__device__ __forceinline__ void ldsm_x4_t(uint32_t* r, uint32_t addr) {
    asm volatile(
        "ldmatrix.sync.aligned.m8n8.x4.trans.shared.b16 {%0,%1,%2,%3}, [%4];"
        : "=r"(r[0]), "=r"(r[1]), "=r"(r[2]), "=r"(r[3]) : "r"(addr));
}

__device__ __forceinline__ uint32_t smem_addr_u32(const void* p) {
    return (uint32_t)__cvta_generic_to_shared(p);
}

__device__ __forceinline__ uint32_t pack_h2(float a, float b) {
    __half2 h = __floats2half2_rn(a, b);
    return *(uint32_t*)&h;
}

// ---------------------------------------------------------------------------
// fp32 -> fp16 convert (vectorized)
// ---------------------------------------------------------------------------
__global__ void to_f16_kernel(const float4* __restrict__ src,
                              __half* __restrict__ dst, int n4)
{
    int i = blockIdx.x * blockDim.x + threadIdx.x;
    if (i >= n4) return;
    float4 v = src[i];
    uint2 o;
    o.x = pack_h2(v.x, v.y);
    o.y = pack_h2(v.z, v.w);
    *(uint2*)(dst + (size_t)i * 4) = o;
}

// ---------------------------------------------------------------------------
// fp16 tensor-core GEMM (NT): C[M,N] = A[M,1280] @ B[N,1280]^T + bias[N]
// BM=BN=128, BK=32 halves, 256 threads (8 warps, 2Mx4N, warp tile 64x32).
// 4-stage cp.async pipeline; all fragments via ldmatrix, batch-then-compute.
// ---------------------------------------------------------------------------
#define GLDH 40                            // smem row stride in halves
#define STAGES 4
#define STAGE_BYTES (128 * GLDH * 2)       // 10240
#define GEMM_SMEM (STAGES * 2 * STAGE_BYTES)  // 81920

__global__ __launch_bounds__(256, 2) void gemm_f16_pipe(
    const __half* __restrict__ A, const __half* __restrict__ B,
    const float* __restrict__ bias, void* __restrict__ Cout,
    int N, int half_out)
{
    extern __shared__ __half smp[];
    __half* As = smp;                                 // [STAGES][128][GLDH]
    __half* Bs = smp + STAGES * 128 * GLDH;

    const int tid = threadIdx.x;
    const int lane = tid & 31;
    const int wid = tid >> 5;
    const int wm = (wid & 1) * 64;
    const int wn = (wid >> 1) * 32;
    const int bm = blockIdx.y * 128;
    const int bn = blockIdx.x * 128;

    const int lrow = tid >> 1;            // 0..127
    const int lhh = (tid & 1) * 16;       // halves 0 or 16
    const __half* Ag = A + (size_t)(bm + lrow) * GK + lhh;
    const __half* Bg = B + (size_t)(bn + lrow) * GK + lhh;

    const uint32_t As_base = smem_addr_u32(As);
    const uint32_t Bs_base = smem_addr_u32(Bs);
    const uint32_t sA = As_base + (uint32_t)(lrow * GLDH + lhh) * 2;
    const uint32_t sB = Bs_base + (uint32_t)(lrow * GLDH + lhh) * 2;

    // ldmatrix lane offsets (bytes within a stage)
    const uint32_t a_off = ((uint32_t)(wm + (lane & 15)) * GLDH +
                            ((lane >> 4) << 3)) * 2;
    const uint32_t b_off = ((uint32_t)(wn + (lane & 7) + ((lane >> 4) << 3)) * GLDH +
                            (((lane >> 3) & 1) << 3)) * 2;

    float acc[4][4][4];
#pragma unroll
    for (int i = 0; i < 4; i++)
#pragma unroll
        for (int j = 0; j < 4; j++)
#pragma unroll
            for (int c = 0; c < 4; c++) acc[i][j][c] = 0.f;

#define ISSUE(ktv) do {                                                      \
    const int _st = (ktv) % STAGES;                                          \
    const __half* _ap = Ag + (ktv) * GBK;                                    \
    const __half* _bp = Bg + (ktv) * GBK;                                    \
    uint32_t _da = sA + _st * STAGE_BYTES;                                   \
    uint32_t _db = sB + _st * STAGE_BYTES;                                   \
    asm volatile(                                                            \
        "cp.async.cg.shared.global [%0], [%1], 16;\n\t"                      \
        "cp.async.cg.shared.global [%2], [%3], 16;\n\t"                      \
        "cp.async.cg.shared.global [%4], [%5], 16;\n\t"                      \
        "cp.async.cg.shared.global [%6], [%7], 16;\n\t"                      \
        "cp.async.commit_group;"                                             \
        :: "r"(_da), "l"(_ap), "r"(_da + 16), "l"(_ap + 8),                  \
           "r"(_db), "l"(_bp), "r"(_db + 16), "l"(_bp + 8) : "memory");      \
} while (0)

#pragma unroll
    for (int s = 0; s < STAGES - 1; s++) ISSUE(s);

    for (int kt = 0; kt < GNT; ++kt) {
        const int st = kt % STAGES;
        asm volatile("cp.async.wait_group %0;" :: "n"(STAGES - 2));
        __syncthreads();
        if (kt + STAGES - 1 < GNT) ISSUE(kt + STAGES - 1);

        const uint32_t a_base = As_base + st * STAGE_BYTES + a_off;
        const uint32_t b_base = Bs_base + st * STAGE_BYTES + b_off;

        // Batch ALL fragment loads (both k-steps), then all MMAs.
        uint32_t af[2][4][4], bq[2][2][4];
#pragma unroll
        for (int ks = 0; ks < 2; ++ks) {
            const uint32_t kcb = ks * 16 * 2;
#pragma unroll
            for (int i = 0; i < 4; i++)
                ldsm_x4(af[ks][i], a_base + (uint32_t)(i * 16 * GLDH * 2) + kcb);
#pragma unroll
            for (int jp = 0; jp < 2; jp++)
                ldsm_x4(bq[ks][jp], b_base + (uint32_t)(jp * 16 * GLDH * 2) + kcb);
        }
#pragma unroll
        for (int ks = 0; ks < 2; ++ks)
#pragma unroll
            for (int i = 0; i < 4; i++)
#pragma unroll
                for (int j = 0; j < 4; j++)
                    mma_f16(acc[i][j], af[ks][i], &bq[ks][j >> 1][(j & 1) * 2]);
    }
#undef ISSUE

    const int r = lane >> 2;
    const int cq = lane & 3;
#pragma unroll
    for (int i = 0; i < 4; i++) {
        const int row0 = bm + wm + i * 16 + r;
#pragma unroll
        for (int j = 0; j < 4; j++) {
            const int col = bn + wn + j * 8 + cq * 2;
            const float b0 = bias[col], b1 = bias[col + 1];
            if (half_out) {
                __half* C16 = (__half*)Cout;
                *(uint32_t*)(C16 + (size_t)row0 * N + col) =
                    pack_h2(acc[i][j][0] + b0, acc[i][j][1] + b1);
                *(uint32_t*)(C16 + (size_t)(row0 + 8) * N + col) =
                    pack_h2(acc[i][j][2] + b0, acc[i][j][3] + b1);
            } else {
                float* C32 = (float*)Cout;
                float2 v;
                v.x = acc[i][j][0] + b0; v.y = acc[i][j][1] + b1;
                *(float2*)(C32 + (size_t)row0 * N + col) = v;
                v.x = acc[i][j][2] + b0; v.y = acc[i][j][3] + b1;
                *(float2*)(C32 + (size_t)(row0 + 8) * N + col) = v;
            }
        }
    }
}

// ---------------------------------------------------------------------------
// RoPE on fp16 qkv: q <- (q*cos + rot(q)*sin)*scale, k <- k*cos + rot(k)*sin
// ---------------------------------------------------------------------------
__global__ void rope16_kernel(const float* __restrict__ cosp,
                              const float* __restrict__ sinp)
{
    int idx = blockIdx.x * blockDim.x + threadIdx.x;
    if (idx >= S_TOK * DIM) return;
    int s = idx / DIM;
    int c = idx - s * DIM;
    int d = c % DH;
    float cv = cosp[s * DH + d];
    float sv = sinp[s * DH + d];
    const __half* row = g_qkv16 + (size_t)s * DIM3;
    float qv = __half2float(row[c]);
    float kv = __half2float(row[DIM + c]);
    float qr, kr;
    if (d < DH / 2) {
        qr = -__half2float(row[c + DH / 2]);
        kr = -__half2float(row[DIM + c + DH / 2]);
    } else {
        qr = __half2float(row[c - DH / 2]);
        kr = __half2float(row[DIM + c - DH / 2]);
    }
    const float scale = 0.11180339887498949f; // 1/sqrt(80)
    g_q16[idx] = __float2half_rn(fmaf(qv, cv, qr * sv) * scale);
    g_k16[idx] = __float2half_rn(fmaf(kv, cv, kr * sv));
}

// ---------------------------------------------------------------------------
// fp16 tensor-core flash attention. Block = 128 Q rows x (seg, head);
// 8 warps x 16 rows. Double-buffered cp.async K/V; K via ldmatrix,
// V via ldmatrix.trans; P packs locally into A-frags (no shuffles).
// ---------------------------------------------------------------------------
#define KVLD 88                            // K/V smem row stride (halves)
#define KVBUF_BYTES (64 * KVLD * 2)        // 11264
#define ATT_SMEM (4 * KVBUF_BYTES)         // 45056

__global__ __launch_bounds__(256, 2) void attn_f16()
{
    extern __shared__ __half asmem[];
    const uint32_t Ks_base = smem_addr_u32(asmem);
    const uint32_t Vs_base = Ks_base + 2 * KVBUF_BYTES;

    const int tid = threadIdx.x;
    const int lane = tid & 31;
    const int w = tid >> 5;
    const int r = lane >> 2;
    const int cq = lane & 3;

    const int qb = blockIdx.x;
    const int h = blockIdx.y;
    const int seg = blockIdx.z;
    const int qrow = seg * SEGLEN + qb * 128 + w * 16;
    const int hoff = h * DH;

#define AISSUE(kvtv, buf) do {                                               \
    const int _tb = seg * SEGLEN + (kvtv) * 64;                              \
    for (int _c = tid; _c < 640; _c += 256) {                                \
        int _row = _c / 10, _c16 = _c - _row * 10;                           \
        uint32_t _kd = Ks_base + (buf) * KVBUF_BYTES + _row * (KVLD * 2) + _c16 * 16; \
        uint32_t _vd = Vs_base + (buf) * KVBUF_BYTES + _row * (KVLD * 2) + _c16 * 16; \
        const __half* _kp = g_k16 + (size_t)(_tb + _row) * DIM + hoff + _c16 * 8; \
        const __half* _vp = g_qkv16 + (size_t)(_tb + _row) * DIM3 + 2 * DIM + hoff + _c16 * 8; \
        asm volatile(                                                        \
            "cp.async.cg.shared.global [%0], [%1], 16;\n\t"                  \
            "cp.async.cg.shared.global [%2], [%3], 16;\n\t"                  \
            :: "r"(_kd), "l"(_kp), "r"(_vd), "l"(_vp) : "memory");           \
    }                                                                        \
    asm volatile("cp.async.commit_group;" ::: "memory");                     \
} while (0)

    // Q fragments: 5 k-steps of 16 halves
    uint32_t qa[5][4];
    {
        const __half* Qb = g_q16 + (size_t)qrow * DIM + hoff;
#pragma unroll
        for (int ks = 0; ks < 5; ks++) {
            qa[ks][0] = *(const uint32_t*)(Qb + (size_t)r * DIM + ks * 16 + 2 * cq);
            qa[ks][1] = *(const uint32_t*)(Qb + (size_t)(r + 8) * DIM + ks * 16 + 2 * cq);
            qa[ks][2] = *(const uint32_t*)(Qb + (size_t)r * DIM + ks * 16 + 8 + 2 * cq);
            qa[ks][3] = *(const uint32_t*)(Qb + (size_t)(r + 8) * DIM + ks * 16 + 8 + 2 * cq);
        }
    }

    float m0 = -1e30f, m1 = -1e30f, l0 = 0.f, l1 = 0.f;
    float oacc[10][4];
#pragma unroll
    for (int v = 0; v < 10; v++)
#pragma unroll
        for (int c = 0; c < 4; c++) oacc[v][c] = 0.f;

    // ldmatrix lane offsets (bytes within a buffer)
    const uint32_t kb_off = ((uint32_t)((lane & 7) + ((lane >> 4) << 3)) * KVLD +
                            (((lane >> 3) & 1) << 3)) * 2;
    const uint32_t vb_off = ((uint32_t)((lane & 7) + (((lane >> 3) & 1) << 3)) * KVLD +
                            (((lane >> 4) & 1) << 3)) * 2;

    AISSUE(0, 0);

    for (int kvt = 0; kvt < 16; kvt++) {
        const int buf = kvt & 1;
        asm volatile("cp.async.wait_group 0;" ::: "memory");
        __syncthreads();
        if (kvt + 1 < 16) AISSUE(kvt + 1, buf ^ 1);

        const uint32_t kbase = Ks_base + buf * KVBUF_BYTES + kb_off;
        const uint32_t vbase = Vs_base + buf * KVBUF_BYTES + vb_off;

        // S = Q K^T : per k-step, batch 4 LDSM then 8 MMA
        float sc[8][4];
#pragma unroll
        for (int j = 0; j < 8; j++)
#pragma unroll
            for (int c = 0; c < 4; c++) sc[j][c] = 0.f;

#pragma unroll
        for (int ks = 0; ks < 5; ks++) {
            uint32_t bq[4][4];
#pragma unroll
            for (int jp = 0; jp < 4; jp++)
                ldsm_x4(bq[jp], kbase + (uint32_t)(jp * 16 * KVLD * 2) +
                                (uint32_t)(ks * 32));
#pragma unroll
            for (int jp = 0; jp < 4; jp++) {
                mma_f16(sc[jp * 2], qa[ks], &bq[jp][0]);
                mma_f16(sc[jp * 2 + 1], qa[ks], &bq[jp][2]);
            }
        }

        // Online softmax (C-frag layout: rows r / r+8)
        float mx0 = -1e30f, mx1 = -1e30f;
#pragma unroll
        for (int j = 0; j < 8; j++) {
            mx0 = fmaxf(mx0, fmaxf(sc[j][0], sc[j][1]));
            mx1 = fmaxf(mx1, fmaxf(sc[j][2], sc[j][3]));
        }
        mx0 = fmaxf(mx0, __shfl_xor_sync(0xffffffffu, mx0, 1));
        mx0 = fmaxf(mx0, __shfl_xor_sync(0xffffffffu, mx0, 2));
        mx1 = fmaxf(mx1, __shfl_xor_sync(0xffffffffu, mx1, 1));
        mx1 = fmaxf(mx1, __shfl_xor_sync(0xffffffffu, mx1, 2));
        const float nm0 = fmaxf(m0, mx0);
        const float nm1 = fmaxf(m1, mx1);
        const float corr0 = __expf(m0 - nm0);
        const float corr1 = __expf(m1 - nm1);
        m0 = nm0; m1 = nm1;

        float sum0 = 0.f, sum1 = 0.f;
#pragma unroll
        for (int j = 0; j < 8; j++) {
            sc[j][0] = __expf(sc[j][0] - nm0);
            sc[j][1] = __expf(sc[j][1] - nm0);
            sc[j][2] = __expf(sc[j][2] - nm1);
            sc[j][3] = __expf(sc[j][3] - nm1);
            sum0 += sc[j][0] + sc[j][1];
            sum1 += sc[j][2] + sc[j][3];
        }
        sum0 += __shfl_xor_sync(0xffffffffu, sum0, 1);
        sum0 += __shfl_xor_sync(0xffffffffu, sum0, 2);
        sum1 += __shfl_xor_sync(0xffffffffu, sum1, 1);
        sum1 += __shfl_xor_sync(0xffffffffu, sum1, 2);
        l0 = l0 * corr0 + sum0;
        l1 = l1 * corr1 + sum1;

#pragma unroll
        for (int v = 0; v < 10; v++) {
            oacc[v][0] *= corr0; oacc[v][1] *= corr0;
            oacc[v][2] *= corr1; oacc[v][3] *= corr1;
        }

        // O += P V : P packs locally (C-frag -> fp16 A-frag is lane-local)
#pragma unroll
        for (int t = 0; t < 4; t++) {
            uint32_t pa[4];
            pa[0] = pack_h2(sc[2 * t][0], sc[2 * t][1]);
            pa[1] = pack_h2(sc[2 * t][2], sc[2 * t][3]);
            pa[2] = pack_h2(sc[2 * t + 1][0], sc[2 * t + 1][1]);
            pa[3] = pack_h2(sc[2 * t + 1][2], sc[2 * t + 1][3]);
#pragma unroll
            for (int vp = 0; vp < 5; vp++) {
                uint32_t bv[4];
                ldsm_x4_t(bv, vbase + (uint32_t)(t * 16 * KVLD * 2) +
                              (uint32_t)(vp * 32));
                mma_f16(oacc[2 * vp], pa, &bv[0]);
                mma_f16(oacc[2 * vp + 1], pa, &bv[2]);
            }
        }
    }
#undef AISSUE

    // Epilogue: fp16 out (proj GEMM input)
    const float inv0 = 1.f / l0;
    const float inv1 = 1.f / l1;
    __half* O0 = g_attn16 + (size_t)(qrow + r) * DIM + hoff;
    __half* O1 = g_attn16 + (size_t)(qrow + r + 8) * DIM + hoff;
#pragma unroll
    for (int v = 0; v < 10; v++) {
        *(uint32_t*)(O0 + v * 8 + 2 * cq) =
            pack_h2(oacc[v][0] * inv0, oacc[v][1] * inv0);
        *(uint32_t*)(O1 + v * 8 + 2 * cq) =
            pack_h2(oacc[v][2] * inv1, oacc[v][3] * inv1);
    }
}

// ---------------------------------------------------------------------------
extern "C" void kernel_launch(void* const* d_in, const int* in_sizes, int n_in,
                              void* d_out, int out_size)
{
    const float* hs     = (const float*)d_in[0];
    const float* cosp   = (const float*)d_in[1];
    const float* sinp   = (const float*)d_in[2];
    const float* qkv_w  = (const float*)d_in[3];
    const float* qkv_b  = (const float*)d_in[4];
    const float* proj_w = (const float*)d_in[5];
    const float* proj_b = (const float*)d_in[6];
    float* out = (float*)d_out;

    __half *qkv_p, *attn_p, *hs_p, *wq_p, *wp_p;
    cudaGetSymbolAddress((void**)&qkv_p, g_qkv16);
    cudaGetSymbolAddress((void**)&attn_p, g_attn16);
    cudaGetSymbolAddress((void**)&hs_p, g_hs16);
    cudaGetSymbolAddress((void**)&wq_p, g_wq16);
    cudaGetSymbolAddress((void**)&wp_p, g_wp16);

    cudaFuncSetAttribute(gemm_f16_pipe,
                         cudaFuncAttributeMaxDynamicSharedMemorySize, GEMM_SMEM);
    cudaFuncSetAttribute(attn_f16,
                         cudaFuncAttributeMaxDynamicSharedMemorySize, ATT_SMEM);

    // 0) Convert GEMM inputs to fp16
    {
        int n4 = S_TOK * DIM / 4;
        to_f16_kernel<<<(n4 + 255) / 256, 256>>>((const float4*)hs, hs_p, n4);
        n4 = DIM3 * DIM / 4;
        to_f16_kernel<<<(n4 + 255) / 256, 256>>>((const float4*)qkv_w, wq_p, n4);
        n4 = DIM * DIM / 4;
        to_f16_kernel<<<(n4 + 255) / 256, 256>>>((const float4*)proj_w, wp_p, n4);
    }

    // 1) QKV GEMM + bias (fp16 tensor cores), fp16 output
    dim3 g1(DIM3 / 128, S_TOK / 128);
    gemm_f16_pipe<<<g1, 256, GEMM_SMEM>>>(hs_p, wq_p, qkv_b, qkv_p, DIM3, 1);

    // 2) RoPE (folds softmax scale into Q)
    int total = S_TOK * DIM;
    rope16_kernel<<<(total + 255) / 256, 256>>>(cosp, sinp);

    // 3) fp16 tensor-core flash attention
    dim3 g2(SEGLEN / 128, NH, NSEG);
    attn_f16<<<g2, 256, ATT_SMEM>>>();

    // 4) Output projection + bias (fp32 output)
    dim3 g3(DIM / 128, S_TOK / 128);
    gemm_f16_pipe<<<g3, 256, GEMM_SMEM>>>(attn_p, wp_p, proj_b, out, DIM, 0);
}